// round 3
// baseline (speedup 1.0000x reference)
#include <cuda_runtime.h>
#include <math.h>

#define Bn 2
#define Sn 2048
#define Dn 1024
#define Hn 16
#define HDn 64
#define NEGV -1.0e9f

// Scratch (device globals: no allocations allowed)
__device__ float g_qh[Bn*Hn*Sn*HDn];   // [B,H,S,HD]
__device__ float g_kh[Bn*Hn*Sn*HDn];
__device__ float g_vh[Bn*Hn*Sn*HDn];
__device__ float g_ctx[Bn*Sn*Dn];      // [B,S,D] context before Wo

// ---------------------------------------------------------------------------
// GEMM: Y[n,m] = sum_k X[n,k]*W[m,k] + bias[m]   (torch Linear, NT form)
// N=4096 rows, M=1024 cols, K=1024.
// BM=128, BN=64, BK=16, 256 threads, 8x4 per-thread tile.
// HEAD_OUT=1: write to [B,H,S,HD] layout; HEAD_OUT=0: plain [N,M] row-major.
// ---------------------------------------------------------------------------
template<int HEAD_OUT>
__global__ void __launch_bounds__(256) gemm_nt(const float* __restrict__ X,
                                               const float* __restrict__ W,
                                               const float* __restrict__ bias,
                                               float* __restrict__ Y)
{
    __shared__ float Xs[16][132];  // [k][m], padded
    __shared__ float Ws[16][68];   // [k][n], padded

    const int t  = threadIdx.x;
    const int ty = t >> 4;         // 0..15  (M groups of 8)
    const int tx = t & 15;         // 0..15  (N groups of 4)
    const int rowBase = blockIdx.y * 128;
    const int colBase = blockIdx.x * 64;

    float acc[8][4];
#pragma unroll
    for (int i = 0; i < 8; i++)
#pragma unroll
        for (int j = 0; j < 4; j++) acc[i][j] = 0.f;

    const int lr = t >> 2;          // 0..63
    const int lk = (t & 3) * 4;     // 0,4,8,12

    for (int k0 = 0; k0 < Dn; k0 += 16) {
        float4 xa = *(const float4*)&X[(size_t)(rowBase + lr) * Dn + k0 + lk];
        float4 xb = *(const float4*)&X[(size_t)(rowBase + lr + 64) * Dn + k0 + lk];
        float4 wa = *(const float4*)&W[(size_t)(colBase + lr) * Dn + k0 + lk];

        Xs[lk + 0][lr] = xa.x; Xs[lk + 1][lr] = xa.y;
        Xs[lk + 2][lr] = xa.z; Xs[lk + 3][lr] = xa.w;
        Xs[lk + 0][lr + 64] = xb.x; Xs[lk + 1][lr + 64] = xb.y;
        Xs[lk + 2][lr + 64] = xb.z; Xs[lk + 3][lr + 64] = xb.w;
        Ws[lk + 0][lr] = wa.x; Ws[lk + 1][lr] = wa.y;
        Ws[lk + 2][lr] = wa.z; Ws[lk + 3][lr] = wa.w;
        __syncthreads();

#pragma unroll
        for (int kk = 0; kk < 16; kk++) {
            float4 a0 = *(float4*)&Xs[kk][ty * 8];
            float4 a1 = *(float4*)&Xs[kk][ty * 8 + 4];
            float4 b0 = *(float4*)&Ws[kk][tx * 4];
            float av[8] = {a0.x, a0.y, a0.z, a0.w, a1.x, a1.y, a1.z, a1.w};
            float bv[4] = {b0.x, b0.y, b0.z, b0.w};
#pragma unroll
            for (int i = 0; i < 8; i++)
#pragma unroll
                for (int j = 0; j < 4; j++)
                    acc[i][j] = fmaf(av[i], bv[j], acc[i][j]);
        }
        __syncthreads();
    }

#pragma unroll
    for (int i = 0; i < 8; i++) {
        const int n = rowBase + ty * 8 + i;
#pragma unroll
        for (int j = 0; j < 4; j++) {
            const int col = colBase + tx * 4 + j;
            const float val = acc[i][j] + bias[col];
            if (HEAD_OUT) {
                const int b = n >> 11;        // /S
                const int s = n & (Sn - 1);
                const int h = col >> 6;       // /HD
                const int d = col & (HDn - 1);
                Y[(size_t)((b * Hn + h) * Sn + s) * HDn + d] = val;
            } else {
                Y[(size_t)n * Dn + col] = val;
            }
        }
    }
}

// ---------------------------------------------------------------------------
// Flash attention, fp32. BQ=BK=64, HD=64. 256 threads, 16x16 thread grid,
// 4x4 score tile per thread. Causal: only key tiles kt <= qt.
// ---------------------------------------------------------------------------
__global__ void __launch_bounds__(256) flash_attn(const float* __restrict__ qh,
                                                  const float* __restrict__ kh,
                                                  const float* __restrict__ vh,
                                                  const int* __restrict__ pad,
                                                  float* __restrict__ ctx)
{
    extern __shared__ float sm[];
    float* Qs = sm;              // [d][q]  64x64
    float* Ks = Qs + 4096;       // [d][n]  64x64
    float* Vs = Ks + 4096;       // [k][d]  64x64
    float* Ps = Vs + 4096;       // [k][q]  64x65 (padded)
    float* PM = Ps + 64 * 65;    // [64] pad flags

    const int t  = threadIdx.x;
    const int ty = t >> 4;       // query group
    const int tx = t & 15;       // key/d group
    const int qt = blockIdx.x;
    const int h  = blockIdx.y;
    const int b  = blockIdx.z;
    const int q0 = qt * 64;

    const float* qb = qh + (size_t)((b * Hn + h) * Sn + q0) * HDn;
    const float* kb = kh + (size_t)((b * Hn + h) * Sn) * HDn;
    const float* vb = vh + (size_t)((b * Hn + h) * Sn) * HDn;

    const int lr  = t >> 2;       // 0..63
    const int ld0 = (t & 3) * 4;  // 0,4,8,12

    // Load Q tile transposed: Qs[d][q]
#pragma unroll
    for (int it = 0; it < 4; it++) {
        const int dd = ld0 + 16 * it;
        float4 v = *(const float4*)&qb[lr * HDn + dd];
        Qs[(dd + 0) * 64 + lr] = v.x;
        Qs[(dd + 1) * 64 + lr] = v.y;
        Qs[(dd + 2) * 64 + lr] = v.z;
        Qs[(dd + 3) * 64 + lr] = v.w;
    }

    float o[4][4];
    float mreg[4], lreg[4];
#pragma unroll
    for (int i = 0; i < 4; i++) {
        mreg[i] = -1e30f;
        lreg[i] = 0.f;
#pragma unroll
        for (int j = 0; j < 4; j++) o[i][j] = 0.f;
    }

    for (int kt = 0; kt <= qt; kt++) {
        const int k0 = kt * 64;
        __syncthreads();  // previous iter's Ks/Vs/Ps reads done; Qs visible on iter 0

        // K tile transposed: Ks[d][n]
#pragma unroll
        for (int it = 0; it < 4; it++) {
            const int dd = ld0 + 16 * it;
            float4 v = *(const float4*)&kb[(size_t)(k0 + lr) * HDn + dd];
            Ks[(dd + 0) * 64 + lr] = v.x;
            Ks[(dd + 1) * 64 + lr] = v.y;
            Ks[(dd + 2) * 64 + lr] = v.z;
            Ks[(dd + 3) * 64 + lr] = v.w;
        }
        // V tile natural [k][d] — tile is contiguous in memory
        {
            const float4* vsrc = (const float4*)&vb[(size_t)k0 * HDn];
            float4* vdst = (float4*)Vs;
#pragma unroll
            for (int it = 0; it < 4; it++) vdst[t + 256 * it] = vsrc[t + 256 * it];
        }
        if (t < 64) PM[t] = (pad[b * Sn + k0 + t] != 0) ? 1.f : 0.f;
        __syncthreads();

        // Score tile: s[q][n] = sum_d Q[q][d] * K[n][d]
        float s[4][4];
#pragma unroll
        for (int i = 0; i < 4; i++)
#pragma unroll
            for (int j = 0; j < 4; j++) s[i][j] = 0.f;

#pragma unroll 8
        for (int dd = 0; dd < 64; dd++) {
            float4 a  = *(float4*)&Qs[dd * 64 + ty * 4];
            float4 bb = *(float4*)&Ks[dd * 64 + tx * 4];
            float av[4] = {a.x, a.y, a.z, a.w};
            float bv[4] = {bb.x, bb.y, bb.z, bb.w};
#pragma unroll
            for (int i = 0; i < 4; i++)
#pragma unroll
                for (int j = 0; j < 4; j++)
                    s[i][j] = fmaf(av[i], bv[j], s[i][j]);
        }

        // Scale + masks (replace semantics, exactly like reference)
#pragma unroll
        for (int i = 0; i < 4; i++) {
            const int q = q0 + ty * 4 + i;
#pragma unroll
            for (int j = 0; j < 4; j++) {
                const int k = k0 + tx * 4 + j;
                float v = s[i][j] * 0.125f;
                if (k > q || PM[tx * 4 + j] != 0.f) v = NEGV;
                s[i][j] = v;
            }
        }

        // Online softmax per query row (reduce across 16 tx lanes)
#pragma unroll
        for (int i = 0; i < 4; i++) {
            float tm = fmaxf(fmaxf(s[i][0], s[i][1]), fmaxf(s[i][2], s[i][3]));
#pragma unroll
            for (int off = 8; off; off >>= 1)
                tm = fmaxf(tm, __shfl_xor_sync(0xffffffffu, tm, off));
            const float mnew = fmaxf(mreg[i], tm);
            const float p0 = expf(s[i][0] - mnew);
            const float p1 = expf(s[i][1] - mnew);
            const float p2 = expf(s[i][2] - mnew);
            const float p3 = expf(s[i][3] - mnew);
            float rs = p0 + p1 + p2 + p3;
#pragma unroll
            for (int off = 8; off; off >>= 1)
                rs += __shfl_xor_sync(0xffffffffu, rs, off);
            const float sc = expf(mreg[i] - mnew);
            lreg[i] = lreg[i] * sc + rs;
            mreg[i] = mnew;
            o[i][0] *= sc; o[i][1] *= sc; o[i][2] *= sc; o[i][3] *= sc;
            Ps[(tx * 4 + 0) * 65 + ty * 4 + i] = p0;
            Ps[(tx * 4 + 1) * 65 + ty * 4 + i] = p1;
            Ps[(tx * 4 + 2) * 65 + ty * 4 + i] = p2;
            Ps[(tx * 4 + 3) * 65 + ty * 4 + i] = p3;
        }
        __syncthreads();

        // O += P @ V
#pragma unroll 4
        for (int k = 0; k < 64; k++) {
            float4 vv = *(float4*)&Vs[k * 64 + tx * 4];
            const float pp0 = Ps[k * 65 + ty * 4 + 0];
            const float pp1 = Ps[k * 65 + ty * 4 + 1];
            const float pp2 = Ps[k * 65 + ty * 4 + 2];
            const float pp3 = Ps[k * 65 + ty * 4 + 3];
            o[0][0] = fmaf(pp0, vv.x, o[0][0]); o[0][1] = fmaf(pp0, vv.y, o[0][1]);
            o[0][2] = fmaf(pp0, vv.z, o[0][2]); o[0][3] = fmaf(pp0, vv.w, o[0][3]);
            o[1][0] = fmaf(pp1, vv.x, o[1][0]); o[1][1] = fmaf(pp1, vv.y, o[1][1]);
            o[1][2] = fmaf(pp1, vv.z, o[1][2]); o[1][3] = fmaf(pp1, vv.w, o[1][3]);
            o[2][0] = fmaf(pp2, vv.x, o[2][0]); o[2][1] = fmaf(pp2, vv.y, o[2][1]);
            o[2][2] = fmaf(pp2, vv.z, o[2][2]); o[2][3] = fmaf(pp2, vv.w, o[2][3]);
            o[3][0] = fmaf(pp3, vv.x, o[3][0]); o[3][1] = fmaf(pp3, vv.y, o[3][1]);
            o[3][2] = fmaf(pp3, vv.z, o[3][2]); o[3][3] = fmaf(pp3, vv.w, o[3][3]);
        }
    }

    // Normalize + write context in [B,S,D] layout (col = h*HD + d)
#pragma unroll
    for (int i = 0; i < 4; i++) {
        const float inv = 1.f / lreg[i];
        const int q = q0 + ty * 4 + i;
        float* dst = &ctx[(size_t)(b * Sn + q) * Dn + h * HDn + tx * 4];
        dst[0] = o[i][0] * inv;
        dst[1] = o[i][1] * inv;
        dst[2] = o[i][2] * inv;
        dst[3] = o[i][3] * inv;
    }
}

// ---------------------------------------------------------------------------
extern "C" void kernel_launch(void* const* d_in, const int* in_sizes, int n_in,
                              void* d_out, int out_size)
{
    const float* x    = (const float*)d_in[0];   // q input [B,S,D]
    const int*   pm   = (const int*)d_in[1];     // pad_mask [B,S] (int32)
    const float* Wq   = (const float*)d_in[2];
    const float* bq   = (const float*)d_in[3];
    const float* Wk   = (const float*)d_in[4];
    const float* bk   = (const float*)d_in[5];
    const float* Wv   = (const float*)d_in[6];
    const float* bv   = (const float*)d_in[7];
    const float* Wo   = (const float*)d_in[8];
    const float* bo   = (const float*)d_in[9];
    float* out = (float*)d_out;

    float *qh, *kh, *vh, *ctx;
    cudaGetSymbolAddress((void**)&qh,  g_qh);
    cudaGetSymbolAddress((void**)&kh,  g_kh);
    cudaGetSymbolAddress((void**)&vh,  g_vh);
    cudaGetSymbolAddress((void**)&ctx, g_ctx);

    const dim3 gblk(256);
    const dim3 ggrid(Dn / 64, (Bn * Sn) / 128);   // (16, 32)

    gemm_nt<1><<<ggrid, gblk>>>(x, Wq, bq, qh);
    gemm_nt<1><<<ggrid, gblk>>>(x, Wk, bk, kh);
    gemm_nt<1><<<ggrid, gblk>>>(x, Wv, bv, vh);

    const int smem_bytes = (4096 * 3 + 64 * 65 + 64) * sizeof(float);  // 66304 B
    cudaFuncSetAttribute(flash_attn, cudaFuncAttributeMaxDynamicSharedMemorySize,
                         smem_bytes);
    dim3 agrid(Sn / 64, Hn, Bn);  // (32, 16, 2)
    flash_attn<<<agrid, gblk, smem_bytes>>>(qh, kh, vh, pm, ctx);

    gemm_nt<0><<<ggrid, gblk>>>(ctx, Wo, bo, out);
}

// round 5
// speedup vs baseline: 1.5503x; 1.5503x over previous
#include <cuda_runtime.h>
#include <math.h>
#include <cstdint>

#define Bn 2
#define Sn 2048
#define Dn 1024
#define Hn 16
#define HDn 64
#define NEGV -1.0e9f

// Scratch (device globals: no allocations allowed)
__device__ float g_qh[Bn*Hn*Sn*HDn];   // [B,H,S,HD]
__device__ float g_kh[Bn*Hn*Sn*HDn];
__device__ float g_vh[Bn*Hn*Sn*HDn];
__device__ float g_ctx[Bn*Sn*Dn];      // [B,S,D] context before Wo

// ===========================================================================
// tf32 warp-MMA GEMM:  Y[n,m] = X[n,:] . W[m,:] + bias[m]   (torch Linear NT)
// mma.sync.m16n8k8 tf32 (portable PTX path; tcgen05 is sm_103a-only and the
// harness compiles for plain sm_103).
// BM=128, BN=128, BK=32, 256 threads = 8 warps (4x2), warp tile 32x64.
// ===========================================================================
#define BM 128
#define BN 128
#define BK 32
#define PKM 136   // floats per k-row in smem (pad: 136*4B == 17*32B, see swizzle)
#define NSTAGES (Dn / BK)   // 32
#define BUF_WORDS (BK * PKM)            // 4352
#define GEMM_SMEM (4 * BUF_WORDS * 4)   // 2 bufs x (A+B) = 69632 B

__device__ __forceinline__ uint32_t cvt_tf32(float x) {
    uint32_t r;
    asm("cvt.rna.tf32.f32 %0, %1;" : "=r"(r) : "f"(x));
    return r;
}

// Swizzled smem index: k-major, XOR on m-bits[2:4] by k-group.
// Conflict-free for both the transposing stores and all mma fragment loads.
__device__ __forceinline__ int swidx(int k, int m) {
    return k * PKM + (m ^ (((k >> 2) & 7) << 2));
}

__device__ __forceinline__ void mma_tf32(float* c, const uint32_t* a,
                                         uint32_t b0, uint32_t b1) {
    asm volatile(
        "mma.sync.aligned.m16n8k8.row.col.f32.tf32.tf32.f32 "
        "{%0,%1,%2,%3}, {%4,%5,%6,%7}, {%8,%9}, {%0,%1,%2,%3};"
        : "+f"(c[0]), "+f"(c[1]), "+f"(c[2]), "+f"(c[3])
        : "r"(a[0]), "r"(a[1]), "r"(a[2]), "r"(a[3]), "r"(b0), "r"(b1));
}

template<int HEAD_OUT>
__global__ void __launch_bounds__(256) gemm_mma(const float* __restrict__ X,
                                                const float* __restrict__ W,
                                                const float* __restrict__ bias,
                                                float* __restrict__ Y)
{
    extern __shared__ uint32_t smem[];
    uint32_t* sA = smem;                    // [2][BK*PKM]
    uint32_t* sB = smem + 2 * BUF_WORDS;    // [2][BK*PKM]

    const int t  = threadIdx.x;
    const int w  = t >> 5;
    const int ln = t & 31;
    const int g  = ln >> 2;      // groupID 0..7
    const int q  = ln & 3;       // thread-in-group 0..3
    const int wm = (w & 3) * 32; // warp M offset
    const int wn = (w >> 2) * 64;// warp N offset
    const int rowBase = blockIdx.y * BM;
    const int colBase = blockIdx.x * BN;

    float acc[2][8][4];
#pragma unroll
    for (int mt = 0; mt < 2; mt++)
#pragma unroll
        for (int nt = 0; nt < 8; nt++)
#pragma unroll
            for (int r = 0; r < 4; r++) acc[mt][nt][r] = 0.f;

    float4 ra[4], rb[4];

    auto ldg = [&](int s) {
        const int k0 = s * BK;
#pragma unroll
        for (int i = 0; i < 4; i++) {
            const int e = t + 256 * i;
            const int m = e >> 3, kq = e & 7;
            ra[i] = *(const float4*)&X[(size_t)(rowBase + m) * Dn + k0 + kq * 4];
            rb[i] = *(const float4*)&W[(size_t)(colBase + m) * Dn + k0 + kq * 4];
        }
    };

    auto sts = [&](int buf) {
        uint32_t* a = sA + buf * BUF_WORDS;
        uint32_t* b = sB + buf * BUF_WORDS;
#pragma unroll
        for (int i = 0; i < 4; i++) {
            const int e = t + 256 * i;
            const int m = e >> 3, kq = e & 7;
            a[swidx(4 * kq + 0, m)] = cvt_tf32(ra[i].x);
            a[swidx(4 * kq + 1, m)] = cvt_tf32(ra[i].y);
            a[swidx(4 * kq + 2, m)] = cvt_tf32(ra[i].z);
            a[swidx(4 * kq + 3, m)] = cvt_tf32(ra[i].w);
            b[swidx(4 * kq + 0, m)] = cvt_tf32(rb[i].x);
            b[swidx(4 * kq + 1, m)] = cvt_tf32(rb[i].y);
            b[swidx(4 * kq + 2, m)] = cvt_tf32(rb[i].z);
            b[swidx(4 * kq + 3, m)] = cvt_tf32(rb[i].w);
        }
    };

    auto comp = [&](int buf) {
        const uint32_t* a = sA + buf * BUF_WORDS;
        const uint32_t* b = sB + buf * BUF_WORDS;
#pragma unroll
        for (int kk = 0; kk < 4; kk++) {
            const int kb = kk * 8;
            uint32_t af[2][4];
#pragma unroll
            for (int mt = 0; mt < 2; mt++) {
                const int m = wm + mt * 16 + g;
                af[mt][0] = a[swidx(kb + q,     m)];
                af[mt][1] = a[swidx(kb + q,     m + 8)];
                af[mt][2] = a[swidx(kb + q + 4, m)];
                af[mt][3] = a[swidx(kb + q + 4, m + 8)];
            }
#pragma unroll
            for (int nt = 0; nt < 8; nt++) {
                const int n = wn + nt * 8 + g;
                const uint32_t b0 = b[swidx(kb + q,     n)];
                const uint32_t b1 = b[swidx(kb + q + 4, n)];
                mma_tf32(acc[0][nt], af[0], b0, b1);
                mma_tf32(acc[1][nt], af[1], b0, b1);
            }
        }
    };

    ldg(0);
    sts(0);
    __syncthreads();
    for (int s = 0; s < NSTAGES; s++) {
        if (s + 1 < NSTAGES) ldg(s + 1);
        comp(s & 1);
        if (s + 1 < NSTAGES) {
            __syncthreads();
            sts((s + 1) & 1);
            __syncthreads();
        }
    }

    // Epilogue: regs -> GMEM (+bias)
#pragma unroll
    for (int nt = 0; nt < 8; nt++) {
        const int c = colBase + wn + nt * 8 + 2 * q;
        const float b0 = bias[c], b1 = bias[c + 1];
#pragma unroll
        for (int mt = 0; mt < 2; mt++) {
            const int r0 = rowBase + wm + mt * 16 + g;
#pragma unroll
            for (int half = 0; half < 2; half++) {
                const int rr = r0 + half * 8;
                float2 v;
                v.x = acc[mt][nt][half * 2 + 0] + b0;
                v.y = acc[mt][nt][half * 2 + 1] + b1;
                if (HEAD_OUT) {
                    const int bb = rr >> 11;
                    const int ss = rr & (Sn - 1);
                    const int hh = c >> 6;
                    const int dd = c & (HDn - 1);
                    *(float2*)&Y[(size_t)((bb * Hn + hh) * Sn + ss) * HDn + dd] = v;
                } else {
                    *(float2*)&Y[(size_t)rr * Dn + c] = v;
                }
            }
        }
    }
}

// ---------------------------------------------------------------------------
// Flash attention, fp32. BQ=BK=64, HD=64. 256 threads, 16x16 thread grid,
// 4x4 score tile per thread. Causal: only key tiles kt <= qt.  (unchanged)
// ---------------------------------------------------------------------------
__global__ void __launch_bounds__(256) flash_attn(const float* __restrict__ qh,
                                                  const float* __restrict__ kh,
                                                  const float* __restrict__ vh,
                                                  const int* __restrict__ pad,
                                                  float* __restrict__ ctx)
{
    extern __shared__ float sm[];
    float* Qs = sm;              // [d][q]  64x64
    float* Ks = Qs + 4096;       // [d][n]  64x64
    float* Vs = Ks + 4096;       // [k][d]  64x64
    float* Ps = Vs + 4096;       // [k][q]  64x65 (padded)
    float* PM = Ps + 64 * 65;    // [64] pad flags

    const int t  = threadIdx.x;
    const int ty = t >> 4;
    const int tx = t & 15;
    const int qt = blockIdx.x;
    const int h  = blockIdx.y;
    const int b  = blockIdx.z;
    const int q0 = qt * 64;

    const float* qb = qh + (size_t)((b * Hn + h) * Sn + q0) * HDn;
    const float* kb = kh + (size_t)((b * Hn + h) * Sn) * HDn;
    const float* vb = vh + (size_t)((b * Hn + h) * Sn) * HDn;

    const int lr  = t >> 2;
    const int ld0 = (t & 3) * 4;

#pragma unroll
    for (int it = 0; it < 4; it++) {
        const int dd = ld0 + 16 * it;
        float4 v = *(const float4*)&qb[lr * HDn + dd];
        Qs[(dd + 0) * 64 + lr] = v.x;
        Qs[(dd + 1) * 64 + lr] = v.y;
        Qs[(dd + 2) * 64 + lr] = v.z;
        Qs[(dd + 3) * 64 + lr] = v.w;
    }

    float o[4][4];
    float mreg[4], lreg[4];
#pragma unroll
    for (int i = 0; i < 4; i++) {
        mreg[i] = -1e30f;
        lreg[i] = 0.f;
#pragma unroll
        for (int j = 0; j < 4; j++) o[i][j] = 0.f;
    }

    for (int kt = 0; kt <= qt; kt++) {
        const int k0 = kt * 64;
        __syncthreads();

#pragma unroll
        for (int it = 0; it < 4; it++) {
            const int dd = ld0 + 16 * it;
            float4 v = *(const float4*)&kb[(size_t)(k0 + lr) * HDn + dd];
            Ks[(dd + 0) * 64 + lr] = v.x;
            Ks[(dd + 1) * 64 + lr] = v.y;
            Ks[(dd + 2) * 64 + lr] = v.z;
            Ks[(dd + 3) * 64 + lr] = v.w;
        }
        {
            const float4* vsrc = (const float4*)&vb[(size_t)k0 * HDn];
            float4* vdst = (float4*)Vs;
#pragma unroll
            for (int it = 0; it < 4; it++) vdst[t + 256 * it] = vsrc[t + 256 * it];
        }
        if (t < 64) PM[t] = (pad[b * Sn + k0 + t] != 0) ? 1.f : 0.f;
        __syncthreads();

        float s[4][4];
#pragma unroll
        for (int i = 0; i < 4; i++)
#pragma unroll
            for (int j = 0; j < 4; j++) s[i][j] = 0.f;

#pragma unroll 8
        for (int dd = 0; dd < 64; dd++) {
            float4 a  = *(float4*)&Qs[dd * 64 + ty * 4];
            float4 bb = *(float4*)&Ks[dd * 64 + tx * 4];
            float av[4] = {a.x, a.y, a.z, a.w};
            float bv[4] = {bb.x, bb.y, bb.z, bb.w};
#pragma unroll
            for (int i = 0; i < 4; i++)
#pragma unroll
                for (int j = 0; j < 4; j++)
                    s[i][j] = fmaf(av[i], bv[j], s[i][j]);
        }

#pragma unroll
        for (int i = 0; i < 4; i++) {
            const int qq = q0 + ty * 4 + i;
#pragma unroll
            for (int j = 0; j < 4; j++) {
                const int k = k0 + tx * 4 + j;
                float v = s[i][j] * 0.125f;
                if (k > qq || PM[tx * 4 + j] != 0.f) v = NEGV;
                s[i][j] = v;
            }
        }

#pragma unroll
        for (int i = 0; i < 4; i++) {
            float tm = fmaxf(fmaxf(s[i][0], s[i][1]), fmaxf(s[i][2], s[i][3]));
#pragma unroll
            for (int off = 8; off; off >>= 1)
                tm = fmaxf(tm, __shfl_xor_sync(0xffffffffu, tm, off));
            const float mnew = fmaxf(mreg[i], tm);
            const float p0 = expf(s[i][0] - mnew);
            const float p1 = expf(s[i][1] - mnew);
            const float p2 = expf(s[i][2] - mnew);
            const float p3 = expf(s[i][3] - mnew);
            float rs = p0 + p1 + p2 + p3;
#pragma unroll
            for (int off = 8; off; off >>= 1)
                rs += __shfl_xor_sync(0xffffffffu, rs, off);
            const float sc = expf(mreg[i] - mnew);
            lreg[i] = lreg[i] * sc + rs;
            mreg[i] = mnew;
            o[i][0] *= sc; o[i][1] *= sc; o[i][2] *= sc; o[i][3] *= sc;
            Ps[(tx * 4 + 0) * 65 + ty * 4 + i] = p0;
            Ps[(tx * 4 + 1) * 65 + ty * 4 + i] = p1;
            Ps[(tx * 4 + 2) * 65 + ty * 4 + i] = p2;
            Ps[(tx * 4 + 3) * 65 + ty * 4 + i] = p3;
        }
        __syncthreads();

#pragma unroll 4
        for (int k = 0; k < 64; k++) {
            float4 vv = *(float4*)&Vs[k * 64 + tx * 4];
            const float pp0 = Ps[k * 65 + ty * 4 + 0];
            const float pp1 = Ps[k * 65 + ty * 4 + 1];
            const float pp2 = Ps[k * 65 + ty * 4 + 2];
            const float pp3 = Ps[k * 65 + ty * 4 + 3];
            o[0][0] = fmaf(pp0, vv.x, o[0][0]); o[0][1] = fmaf(pp0, vv.y, o[0][1]);
            o[0][2] = fmaf(pp0, vv.z, o[0][2]); o[0][3] = fmaf(pp0, vv.w, o[0][3]);
            o[1][0] = fmaf(pp1, vv.x, o[1][0]); o[1][1] = fmaf(pp1, vv.y, o[1][1]);
            o[1][2] = fmaf(pp1, vv.z, o[1][2]); o[1][3] = fmaf(pp1, vv.w, o[1][3]);
            o[2][0] = fmaf(pp2, vv.x, o[2][0]); o[2][1] = fmaf(pp2, vv.y, o[2][1]);
            o[2][2] = fmaf(pp2, vv.z, o[2][2]); o[2][3] = fmaf(pp2, vv.w, o[2][3]);
            o[3][0] = fmaf(pp3, vv.x, o[3][0]); o[3][1] = fmaf(pp3, vv.y, o[3][1]);
            o[3][2] = fmaf(pp3, vv.z, o[3][2]); o[3][3] = fmaf(pp3, vv.w, o[3][3]);
        }
    }

#pragma unroll
    for (int i = 0; i < 4; i++) {
        const float inv = 1.f / lreg[i];
        const int qq = q0 + ty * 4 + i;
        float* dst = &ctx[(size_t)(b * Sn + qq) * Dn + h * HDn + tx * 4];
        dst[0] = o[i][0] * inv;
        dst[1] = o[i][1] * inv;
        dst[2] = o[i][2] * inv;
        dst[3] = o[i][3] * inv;
    }
}

// ---------------------------------------------------------------------------
extern "C" void kernel_launch(void* const* d_in, const int* in_sizes, int n_in,
                              void* d_out, int out_size)
{
    const float* x    = (const float*)d_in[0];   // q input [B,S,D]
    const int*   pm   = (const int*)d_in[1];     // pad_mask [B,S] (int32)
    const float* Wq   = (const float*)d_in[2];
    const float* bq   = (const float*)d_in[3];
    const float* Wk   = (const float*)d_in[4];
    const float* bk   = (const float*)d_in[5];
    const float* Wv   = (const float*)d_in[6];
    const float* bv   = (const float*)d_in[7];
    const float* Wo   = (const float*)d_in[8];
    const float* bo   = (const float*)d_in[9];
    float* out = (float*)d_out;

    float *qh, *kh, *vh, *ctx;
    cudaGetSymbolAddress((void**)&qh,  g_qh);
    cudaGetSymbolAddress((void**)&kh,  g_kh);
    cudaGetSymbolAddress((void**)&vh,  g_vh);
    cudaGetSymbolAddress((void**)&ctx, g_ctx);

    cudaFuncSetAttribute(gemm_mma<1>, cudaFuncAttributeMaxDynamicSharedMemorySize,
                         GEMM_SMEM);
    cudaFuncSetAttribute(gemm_mma<0>, cudaFuncAttributeMaxDynamicSharedMemorySize,
                         GEMM_SMEM);

    const dim3 tgrid(Dn / BN, (Bn * Sn) / BM);   // (8, 32) = 256 CTAs
    gemm_mma<1><<<tgrid, 256, GEMM_SMEM>>>(x, Wq, bq, qh);
    gemm_mma<1><<<tgrid, 256, GEMM_SMEM>>>(x, Wk, bk, kh);
    gemm_mma<1><<<tgrid, 256, GEMM_SMEM>>>(x, Wv, bv, vh);

    const int smem_bytes = (4096 * 3 + 64 * 65 + 64) * sizeof(float);  // 66304 B
    cudaFuncSetAttribute(flash_attn, cudaFuncAttributeMaxDynamicSharedMemorySize,
                         smem_bytes);
    dim3 agrid(Sn / 64, Hn, Bn);  // (32, 16, 2)
    flash_attn<<<agrid, 256, smem_bytes>>>(qh, kh, vh, pm, ctx);

    gemm_mma<0><<<tgrid, 256, GEMM_SMEM>>>(ctx, Wo, bo, out);
}

// round 9
// speedup vs baseline: 2.6625x; 1.7174x over previous
#include <cuda_runtime.h>
#include <math.h>
#include <cstdint>

#define Bn 2
#define Sn 2048
#define Dn 1024
#define Hn 16
#define HDn 64
#define NEGV -1.0e9f

// Scratch (device globals: no allocations allowed)
__device__ float g_qh[Bn*Hn*Sn*HDn];   // [B,H,S,HD]
__device__ float g_kh[Bn*Hn*Sn*HDn];
__device__ float g_vh[Bn*Hn*Sn*HDn];
__device__ float g_ctx[Bn*Sn*Dn];      // [B,S,D] context before Wo

__device__ __forceinline__ uint32_t cvt_tf32(float x) {
    uint32_t r;
    asm("cvt.rna.tf32.f32 %0, %1;" : "=r"(r) : "f"(x));
    return r;
}

__device__ __forceinline__ void mma_tf32(float* c, const uint32_t* a,
                                         uint32_t b0, uint32_t b1) {
    asm volatile(
        "mma.sync.aligned.m16n8k8.row.col.f32.tf32.tf32.f32 "
        "{%0,%1,%2,%3}, {%4,%5,%6,%7}, {%8,%9}, {%0,%1,%2,%3};"
        : "+f"(c[0]), "+f"(c[1]), "+f"(c[2]), "+f"(c[3])
        : "r"(a[0]), "r"(a[1]), "r"(a[2]), "r"(a[3]), "r"(b0), "r"(b1));
}

// ===========================================================================
// tf32 warp-MMA GEMM:  Y[n,m] = X[n,:] . W[m,:] + bias[m]   (torch Linear NT)
// BM=128, BN=128, BK=32, 256 threads = 8 warps (4x2), warp tile 32x64.
// (unchanged from R5 — passed at ~87us/GEMM)
// ===========================================================================
#define BM 128
#define BN 128
#define BK 32
#define PKM 136
#define NSTAGES (Dn / BK)
#define BUF_WORDS (BK * PKM)            // 4352
#define GEMM_SMEM (4 * BUF_WORDS * 4)   // 69632 B

__device__ __forceinline__ int swidx(int k, int m) {
    return k * PKM + (m ^ (((k >> 2) & 7) << 2));
}

template<int HEAD_OUT>
__global__ void __launch_bounds__(256) gemm_mma(const float* __restrict__ X,
                                                const float* __restrict__ W,
                                                const float* __restrict__ bias,
                                                float* __restrict__ Y)
{
    extern __shared__ uint32_t smem[];
    uint32_t* sA = smem;
    uint32_t* sB = smem + 2 * BUF_WORDS;

    const int t  = threadIdx.x;
    const int w  = t >> 5;
    const int ln = t & 31;
    const int g  = ln >> 2;
    const int q  = ln & 3;
    const int wm = (w & 3) * 32;
    const int wn = (w >> 2) * 64;
    const int rowBase = blockIdx.y * BM;
    const int colBase = blockIdx.x * BN;

    float acc[2][8][4];
#pragma unroll
    for (int mt = 0; mt < 2; mt++)
#pragma unroll
        for (int nt = 0; nt < 8; nt++)
#pragma unroll
            for (int r = 0; r < 4; r++) acc[mt][nt][r] = 0.f;

    float4 ra[4], rb[4];

    auto ldg = [&](int s) {
        const int k0 = s * BK;
#pragma unroll
        for (int i = 0; i < 4; i++) {
            const int e = t + 256 * i;
            const int m = e >> 3, kq = e & 7;
            ra[i] = *(const float4*)&X[(size_t)(rowBase + m) * Dn + k0 + kq * 4];
            rb[i] = *(const float4*)&W[(size_t)(colBase + m) * Dn + k0 + kq * 4];
        }
    };

    auto sts = [&](int buf) {
        uint32_t* a = sA + buf * BUF_WORDS;
        uint32_t* b = sB + buf * BUF_WORDS;
#pragma unroll
        for (int i = 0; i < 4; i++) {
            const int e = t + 256 * i;
            const int m = e >> 3, kq = e & 7;
            a[swidx(4 * kq + 0, m)] = cvt_tf32(ra[i].x);
            a[swidx(4 * kq + 1, m)] = cvt_tf32(ra[i].y);
            a[swidx(4 * kq + 2, m)] = cvt_tf32(ra[i].z);
            a[swidx(4 * kq + 3, m)] = cvt_tf32(ra[i].w);
            b[swidx(4 * kq + 0, m)] = cvt_tf32(rb[i].x);
            b[swidx(4 * kq + 1, m)] = cvt_tf32(rb[i].y);
            b[swidx(4 * kq + 2, m)] = cvt_tf32(rb[i].z);
            b[swidx(4 * kq + 3, m)] = cvt_tf32(rb[i].w);
        }
    };

    auto comp = [&](int buf) {
        const uint32_t* a = sA + buf * BUF_WORDS;
        const uint32_t* b = sB + buf * BUF_WORDS;
#pragma unroll
        for (int kk = 0; kk < 4; kk++) {
            const int kb = kk * 8;
            uint32_t af[2][4];
#pragma unroll
            for (int mt = 0; mt < 2; mt++) {
                const int m = wm + mt * 16 + g;
                af[mt][0] = a[swidx(kb + q,     m)];
                af[mt][1] = a[swidx(kb + q,     m + 8)];
                af[mt][2] = a[swidx(kb + q + 4, m)];
                af[mt][3] = a[swidx(kb + q + 4, m + 8)];
            }
#pragma unroll
            for (int nt = 0; nt < 8; nt++) {
                const int n = wn + nt * 8 + g;
                const uint32_t b0 = b[swidx(kb + q,     n)];
                const uint32_t b1 = b[swidx(kb + q + 4, n)];
                mma_tf32(acc[0][nt], af[0], b0, b1);
                mma_tf32(acc[1][nt], af[1], b0, b1);
            }
        }
    };

    ldg(0);
    sts(0);
    __syncthreads();
    for (int s = 0; s < NSTAGES; s++) {
        if (s + 1 < NSTAGES) ldg(s + 1);
        comp(s & 1);
        if (s + 1 < NSTAGES) {
            __syncthreads();
            sts((s + 1) & 1);
            __syncthreads();
        }
    }

#pragma unroll
    for (int nt = 0; nt < 8; nt++) {
        const int c = colBase + wn + nt * 8 + 2 * q;
        const float b0 = bias[c], b1 = bias[c + 1];
#pragma unroll
        for (int mt = 0; mt < 2; mt++) {
            const int r0 = rowBase + wm + mt * 16 + g;
#pragma unroll
            for (int half = 0; half < 2; half++) {
                const int rr = r0 + half * 8;
                float2 v;
                v.x = acc[mt][nt][half * 2 + 0] + b0;
                v.y = acc[mt][nt][half * 2 + 1] + b1;
                if (HEAD_OUT) {
                    const int bb = rr >> 11;
                    const int ss = rr & (Sn - 1);
                    const int hh = c >> 6;
                    const int dd = c & (HDn - 1);
                    *(float2*)&Y[(size_t)((bb * Hn + hh) * Sn + ss) * HDn + dd] = v;
                } else {
                    *(float2*)&Y[(size_t)rr * Dn + c] = v;
                }
            }
        }
    }
}

// ===========================================================================
// Flash attention on mma.sync tf32. BQ=BK=64, HD=64. 128 threads = 4 warps,
// each warp owns 16 query rows. Smem stride 76 floats: 16B-aligned rows +
// conflict-free fragment loads for both [n][k] and [k][n] access forms.
// ===========================================================================
#define ASTR 76
#define FA_SMEM ((4 * 64 * ASTR + 64) * 4)   // 78080 B

__global__ void __launch_bounds__(128) flash_attn_mma(const float* __restrict__ qh,
                                                      const float* __restrict__ kh,
                                                      const float* __restrict__ vh,
                                                      const int* __restrict__ pad,
                                                      float* __restrict__ ctx)
{
    extern __shared__ uint32_t sm[];
    uint32_t* Qs = sm;                 // [query][d]   tf32, row stride 76
    uint32_t* Ks = Qs + 64 * ASTR;     // [key][d]     tf32 (natural)
    uint32_t* Vs = Ks + 64 * ASTR;     // [key][d]     tf32 (natural)
    uint32_t* Ps = Vs + 64 * ASTR;     // [query][key] tf32
    float*    PM = (float*)(Ps + 64 * ASTR);   // [64] pad flags

    const int t  = threadIdx.x;
    const int w  = t >> 5;
    const int ln = t & 31;
    const int g  = ln >> 2;      // 0..7
    const int q  = ln & 3;       // 0..3
    const int qt = blockIdx.x;
    const int h  = blockIdx.y;
    const int b  = blockIdx.z;
    const int q0 = qt * 64;
    const int wq = w * 16;

    const float* qb = qh + (size_t)((b * Hn + h) * Sn + q0) * HDn;
    const float* kb = kh + (size_t)((b * Hn + h) * Sn) * HDn;
    const float* vb = vh + (size_t)((b * Hn + h) * Sn) * HDn;

    // Load Q tile (pre-scaled by 1/sqrt(HD)=0.125, tf32-rounded)
#pragma unroll
    for (int i = 0; i < 8; i++) {
        const int cc  = t + 128 * i;       // 0..1023 float4 chunks
        const int row = cc >> 4;
        const int c4  = cc & 15;
        float4 v = *(const float4*)&qb[row * HDn + c4 * 4];
        uint4 u;
        u.x = cvt_tf32(v.x * 0.125f);
        u.y = cvt_tf32(v.y * 0.125f);
        u.z = cvt_tf32(v.z * 0.125f);
        u.w = cvt_tf32(v.w * 0.125f);
        *(uint4*)&Qs[row * ASTR + c4 * 4] = u;
    }

    float o[8][4];
#pragma unroll
    for (int dt = 0; dt < 8; dt++)
#pragma unroll
        for (int r = 0; r < 4; r++) o[dt][r] = 0.f;
    float mrow[2] = {-1e30f, -1e30f};
    float lrow[2] = {0.f, 0.f};

    const int r_lo = q0 + wq + g;
    const int r_hi = r_lo + 8;

    for (int kt = 0; kt <= qt; kt++) {
        const int k0 = kt * 64;
        __syncthreads();   // Ks/Vs reuse guard (also covers Qs on iter 0)

        // K and V tiles, natural [key][d] layout, vec4 stores
#pragma unroll
        for (int i = 0; i < 8; i++) {
            const int cc  = t + 128 * i;
            const int row = cc >> 4;
            const int c4  = cc & 15;
            float4 kv = *(const float4*)&kb[(size_t)(k0 + row) * HDn + c4 * 4];
            uint4 uk;
            uk.x = cvt_tf32(kv.x); uk.y = cvt_tf32(kv.y);
            uk.z = cvt_tf32(kv.z); uk.w = cvt_tf32(kv.w);
            *(uint4*)&Ks[row * ASTR + c4 * 4] = uk;
            float4 vv = *(const float4*)&vb[(size_t)(k0 + row) * HDn + c4 * 4];
            uint4 uv;
            uv.x = cvt_tf32(vv.x); uv.y = cvt_tf32(vv.y);
            uv.z = cvt_tf32(vv.z); uv.w = cvt_tf32(vv.w);
            *(uint4*)&Vs[row * ASTR + c4 * 4] = uv;
        }
        if (t < 64) PM[t] = (pad[b * Sn + k0 + t] != 0) ? 1.f : 0.f;
        __syncthreads();

        // ---- S = Q K^T  (scores, pre-scaled) ----
        float sv[8][4];
#pragma unroll
        for (int nt = 0; nt < 8; nt++)
#pragma unroll
            for (int r = 0; r < 4; r++) sv[nt][r] = 0.f;

#pragma unroll
        for (int kk = 0; kk < 8; kk++) {
            const int kb8 = kk * 8;
            uint32_t a[4];
            a[0] = Qs[(wq + g)     * ASTR + kb8 + q];
            a[1] = Qs[(wq + g + 8) * ASTR + kb8 + q];
            a[2] = Qs[(wq + g)     * ASTR + kb8 + q + 4];
            a[3] = Qs[(wq + g + 8) * ASTR + kb8 + q + 4];
#pragma unroll
            for (int nt = 0; nt < 8; nt++) {
                const int n = nt * 8 + g;
                const uint32_t b0 = Ks[n * ASTR + kb8 + q];      // K[n][k]
                const uint32_t b1 = Ks[n * ASTR + kb8 + q + 4];
                mma_tf32(sv[nt], a, b0, b1);
            }
        }

        // ---- mask (replace semantics, same as reference) ----
        const bool diag = (kt == qt);
#pragma unroll
        for (int nt = 0; nt < 8; nt++) {
            const int kx0 = nt * 8 + 2 * q;
            const bool pm0 = PM[kx0] != 0.f;
            const bool pm1 = PM[kx0 + 1] != 0.f;
            const int kg0 = k0 + kx0, kg1 = kg0 + 1;
            if (pm0 || (diag && kg0 > r_lo)) sv[nt][0] = NEGV;
            if (pm1 || (diag && kg1 > r_lo)) sv[nt][1] = NEGV;
            if (pm0 || (diag && kg0 > r_hi)) sv[nt][2] = NEGV;
            if (pm1 || (diag && kg1 > r_hi)) sv[nt][3] = NEGV;
        }

        // ---- online softmax (rows live in lane quads) ----
#pragma unroll
        for (int half = 0; half < 2; half++) {
            const int ci = half * 2;
            float tm = -1e30f;
#pragma unroll
            for (int nt = 0; nt < 8; nt++)
                tm = fmaxf(tm, fmaxf(sv[nt][ci], sv[nt][ci + 1]));
            tm = fmaxf(tm, __shfl_xor_sync(0xffffffffu, tm, 1));
            tm = fmaxf(tm, __shfl_xor_sync(0xffffffffu, tm, 2));
            const float mnew = fmaxf(mrow[half], tm);
            const float sc = expf(mrow[half] - mnew);
            float rs = 0.f;
#pragma unroll
            for (int nt = 0; nt < 8; nt++) {
                const float p0 = expf(sv[nt][ci]     - mnew);
                const float p1 = expf(sv[nt][ci + 1] - mnew);
                sv[nt][ci] = p0; sv[nt][ci + 1] = p1;
                rs += p0 + p1;
            }
            rs += __shfl_xor_sync(0xffffffffu, rs, 1);
            rs += __shfl_xor_sync(0xffffffffu, rs, 2);
            lrow[half] = lrow[half] * sc + rs;
            mrow[half] = mnew;
#pragma unroll
            for (int dt = 0; dt < 8; dt++) {
                o[dt][ci]     *= sc;
                o[dt][ci + 1] *= sc;
            }
        }

        // ---- store P (warp-private rows), tf32 ----
#pragma unroll
        for (int nt = 0; nt < 8; nt++) {
            const int col = nt * 8 + 2 * q;
            uint2 plo, phi;
            plo.x = cvt_tf32(sv[nt][0]); plo.y = cvt_tf32(sv[nt][1]);
            phi.x = cvt_tf32(sv[nt][2]); phi.y = cvt_tf32(sv[nt][3]);
            *(uint2*)&Ps[(wq + g)     * ASTR + col] = plo;
            *(uint2*)&Ps[(wq + g + 8) * ASTR + col] = phi;
        }
        __syncwarp();

        // ---- O += P V ----
#pragma unroll
        for (int kk = 0; kk < 8; kk++) {
            const int kb8 = kk * 8;
            uint32_t a[4];
            a[0] = Ps[(wq + g)     * ASTR + kb8 + q];
            a[1] = Ps[(wq + g + 8) * ASTR + kb8 + q];
            a[2] = Ps[(wq + g)     * ASTR + kb8 + q + 4];
            a[3] = Ps[(wq + g + 8) * ASTR + kb8 + q + 4];
#pragma unroll
            for (int dt = 0; dt < 8; dt++) {
                const int n = dt * 8 + g;
                const uint32_t b0 = Vs[(kb8 + q)     * ASTR + n];  // V[k][n]
                const uint32_t b1 = Vs[(kb8 + q + 4) * ASTR + n];
                mma_tf32(o[dt], a, b0, b1);
            }
        }
    }

    // ---- normalize + write context [B,S,D] ----
    const float inv_lo = 1.f / lrow[0];
    const float inv_hi = 1.f / lrow[1];
#pragma unroll
    for (int dt = 0; dt < 8; dt++) {
        const int col = h * HDn + dt * 8 + 2 * q;
        float2 vlo, vhi;
        vlo.x = o[dt][0] * inv_lo; vlo.y = o[dt][1] * inv_lo;
        vhi.x = o[dt][2] * inv_hi; vhi.y = o[dt][3] * inv_hi;
        *(float2*)&ctx[(size_t)(b * Sn + r_lo) * Dn + col] = vlo;
        *(float2*)&ctx[(size_t)(b * Sn + r_hi) * Dn + col] = vhi;
    }
}

// ---------------------------------------------------------------------------
extern "C" void kernel_launch(void* const* d_in, const int* in_sizes, int n_in,
                              void* d_out, int out_size)
{
    const float* x    = (const float*)d_in[0];   // q input [B,S,D]
    const int*   pm   = (const int*)d_in[1];     // pad_mask [B,S] (int32)
    const float* Wq   = (const float*)d_in[2];
    const float* bq   = (const float*)d_in[3];
    const float* Wk   = (const float*)d_in[4];
    const float* bk   = (const float*)d_in[5];
    const float* Wv   = (const float*)d_in[6];
    const float* bv   = (const float*)d_in[7];
    const float* Wo   = (const float*)d_in[8];
    const float* bo   = (const float*)d_in[9];
    float* out = (float*)d_out;

    float *qh, *kh, *vh, *ctx;
    cudaGetSymbolAddress((void**)&qh,  g_qh);
    cudaGetSymbolAddress((void**)&kh,  g_kh);
    cudaGetSymbolAddress((void**)&vh,  g_vh);
    cudaGetSymbolAddress((void**)&ctx, g_ctx);

    cudaFuncSetAttribute(gemm_mma<1>, cudaFuncAttributeMaxDynamicSharedMemorySize,
                         GEMM_SMEM);
    cudaFuncSetAttribute(gemm_mma<0>, cudaFuncAttributeMaxDynamicSharedMemorySize,
                         GEMM_SMEM);
    cudaFuncSetAttribute(flash_attn_mma, cudaFuncAttributeMaxDynamicSharedMemorySize,
                         FA_SMEM);

    const dim3 tgrid(Dn / BN, (Bn * Sn) / BM);   // (8, 32) = 256 CTAs
    gemm_mma<1><<<tgrid, 256, GEMM_SMEM>>>(x, Wq, bq, qh);
    gemm_mma<1><<<tgrid, 256, GEMM_SMEM>>>(x, Wk, bk, kh);
    gemm_mma<1><<<tgrid, 256, GEMM_SMEM>>>(x, Wv, bv, vh);

    dim3 agrid(Sn / 64, Hn, Bn);  // (32, 16, 2)
    flash_attn_mma<<<agrid, 128, FA_SMEM>>>(qh, kh, vh, pm, ctx);

    gemm_mma<0><<<tgrid, 256, GEMM_SMEM>>>(ctx, Wo, bo, out);
}

// round 10
// speedup vs baseline: 3.4501x; 1.2958x over previous
#include <cuda_runtime.h>
#include <cuda_fp16.h>
#include <math.h>
#include <cstdint>

#define Bn 2
#define Sn 2048
#define Dn 1024
#define Hn 16
#define HDn 64
#define NEGV -1.0e9f

// Scratch (device globals: no allocations allowed)
__device__ float g_qh[Bn*Hn*Sn*HDn];   // [B,H,S,HD]
__device__ float g_kh[Bn*Hn*Sn*HDn];
__device__ float g_vh[Bn*Hn*Sn*HDn];
__device__ float g_ctx[Bn*Sn*Dn];      // [B,S,D] context before Wo

__device__ __forceinline__ uint32_t cvt_tf32(float x) {
    uint32_t r;
    asm("cvt.rna.tf32.f32 %0, %1;" : "=r"(r) : "f"(x));
    return r;
}

__device__ __forceinline__ void mma_tf32(float* c, const uint32_t* a,
                                         uint32_t b0, uint32_t b1) {
    asm volatile(
        "mma.sync.aligned.m16n8k8.row.col.f32.tf32.tf32.f32 "
        "{%0,%1,%2,%3}, {%4,%5,%6,%7}, {%8,%9}, {%0,%1,%2,%3};"
        : "+f"(c[0]), "+f"(c[1]), "+f"(c[2]), "+f"(c[3])
        : "r"(a[0]), "r"(a[1]), "r"(a[2]), "r"(a[3]), "r"(b0), "r"(b1));
}

// fp16 m16n8k16: a regs = 2 adjacent k halves; same index structure as the
// verified tf32 m16n8k8 fragments with k replaced by k-pairs.
__device__ __forceinline__ void mma_f16(float* c, const uint32_t* a,
                                        uint32_t b0, uint32_t b1) {
    asm volatile(
        "mma.sync.aligned.m16n8k16.row.col.f32.f16.f16.f32 "
        "{%0,%1,%2,%3}, {%4,%5,%6,%7}, {%8,%9}, {%0,%1,%2,%3};"
        : "+f"(c[0]), "+f"(c[1]), "+f"(c[2]), "+f"(c[3])
        : "r"(a[0]), "r"(a[1]), "r"(a[2]), "r"(a[3]), "r"(b0), "r"(b1));
}

__device__ __forceinline__ uint32_t pack_h2(float x, float y) {
    __half2 h = __floats2half2_rn(x, y);
    return *reinterpret_cast<uint32_t*>(&h);
}

// ===========================================================================
// fp16 warp-MMA GEMM:  Y[n,m] = X[n,:] . W[m,:] + bias[m]   (torch Linear NT)
// BM=128, BN=128, BK=32 (k-halves = 16 pairs), 256 threads = 8 warps (4x2),
// warp tile 32x64. Smem holds half2 words, PKM=136 swizzle (conflict-free in
// pair units — same derivation as the verified tf32 version).
// QKV=1: fused Q/K/V projections (grid.x = 24, CTA third selects W/bias/out,
//        head-layout output). QKV=0: plain row-major output (Wo).
// ===========================================================================
#define BM 128
#define BN 128
#define BKH 32                           // k elements (halves) per stage
#define NPAIR (BKH / 2)                  // 16 half2 pairs
#define PKM 136
#define NSTAGES (Dn / BKH)               // 32
#define BUF_WORDS (NPAIR * PKM)          // 2176 half2 words
#define GEMM_SMEM (4 * BUF_WORDS * 4)    // 34816 B

__device__ __forceinline__ int swidx(int p, int m) {
    return p * PKM + (m ^ (((p >> 2) & 7) << 2));
}

template<int QKV>
__global__ void __launch_bounds__(256) gemm_h(const float* __restrict__ X,
                                              const float* __restrict__ W0,
                                              const float* __restrict__ W1,
                                              const float* __restrict__ W2,
                                              const float* __restrict__ bias0,
                                              const float* __restrict__ bias1,
                                              const float* __restrict__ bias2,
                                              float* __restrict__ Y0,
                                              float* __restrict__ Y1,
                                              float* __restrict__ Y2)
{
    extern __shared__ uint32_t smem[];
    uint32_t* sA = smem;                    // [2][NPAIR*PKM]
    uint32_t* sB = smem + 2 * BUF_WORDS;

    const int t  = threadIdx.x;
    const int w  = t >> 5;
    const int ln = t & 31;
    const int g  = ln >> 2;
    const int q  = ln & 3;
    const int wm = (w & 3) * 32;
    const int wn = (w >> 2) * 64;
    const int rowBase = blockIdx.y * BM;

    // select W / bias / Y per CTA third (uniform branch)
    int which = 0, colW = blockIdx.x * BN;
    if (QKV) { which = blockIdx.x >> 3; colW = (blockIdx.x & 7) * BN; }
    const float* W    = (which == 0) ? W0 : (which == 1) ? W1 : W2;
    const float* bias = (which == 0) ? bias0 : (which == 1) ? bias1 : bias2;
    float*       Y    = (which == 0) ? Y0 : (which == 1) ? Y1 : Y2;

    float acc[2][8][4];
#pragma unroll
    for (int mt = 0; mt < 2; mt++)
#pragma unroll
        for (int nt = 0; nt < 8; nt++)
#pragma unroll
            for (int r = 0; r < 4; r++) acc[mt][nt][r] = 0.f;

    float4 ra[4], rb[4];

    auto ldg = [&](int s) {
        const int k0 = s * BKH;
#pragma unroll
        for (int i = 0; i < 4; i++) {
            const int e = t + 256 * i;
            const int m = e >> 3, kq = e & 7;   // 128 rows x 8 float4 per tile
            ra[i] = *(const float4*)&X[(size_t)(rowBase + m) * Dn + k0 + kq * 4];
            rb[i] = *(const float4*)&W[(size_t)(colW + m) * Dn + k0 + kq * 4];
        }
    };

    auto sts = [&](int buf) {
        uint32_t* a = sA + buf * BUF_WORDS;
        uint32_t* b = sB + buf * BUF_WORDS;
#pragma unroll
        for (int i = 0; i < 4; i++) {
            const int e = t + 256 * i;
            const int m = e >> 3, kq = e & 7;
            a[swidx(2 * kq + 0, m)] = pack_h2(ra[i].x, ra[i].y);
            a[swidx(2 * kq + 1, m)] = pack_h2(ra[i].z, ra[i].w);
            b[swidx(2 * kq + 0, m)] = pack_h2(rb[i].x, rb[i].y);
            b[swidx(2 * kq + 1, m)] = pack_h2(rb[i].z, rb[i].w);
        }
    };

    auto comp = [&](int buf) {
        const uint32_t* a = sA + buf * BUF_WORDS;
        const uint32_t* b = sB + buf * BUF_WORDS;
#pragma unroll
        for (int kk = 0; kk < 2; kk++) {        // two k16 chunks per stage
            const int kbp = kk * 8;             // pair base
            uint32_t af[2][4];
#pragma unroll
            for (int mt = 0; mt < 2; mt++) {
                const int m = wm + mt * 16 + g;
                af[mt][0] = a[swidx(kbp + q,     m)];
                af[mt][1] = a[swidx(kbp + q,     m + 8)];
                af[mt][2] = a[swidx(kbp + q + 4, m)];
                af[mt][3] = a[swidx(kbp + q + 4, m + 8)];
            }
#pragma unroll
            for (int nt = 0; nt < 8; nt++) {
                const int n = wn + nt * 8 + g;
                const uint32_t b0 = b[swidx(kbp + q,     n)];
                const uint32_t b1 = b[swidx(kbp + q + 4, n)];
                mma_f16(acc[0][nt], af[0], b0, b1);
                mma_f16(acc[1][nt], af[1], b0, b1);
            }
        }
    };

    ldg(0);
    sts(0);
    __syncthreads();
    for (int s = 0; s < NSTAGES; s++) {
        if (s + 1 < NSTAGES) ldg(s + 1);
        comp(s & 1);
        if (s + 1 < NSTAGES) {
            __syncthreads();
            sts((s + 1) & 1);
            __syncthreads();
        }
    }

    // Epilogue: regs -> GMEM (+bias)
#pragma unroll
    for (int nt = 0; nt < 8; nt++) {
        const int c = colW + wn + nt * 8 + 2 * q;
        const float b0 = bias[c], b1 = bias[c + 1];
#pragma unroll
        for (int mt = 0; mt < 2; mt++) {
            const int r0 = rowBase + wm + mt * 16 + g;
#pragma unroll
            for (int half = 0; half < 2; half++) {
                const int rr = r0 + half * 8;
                float2 v;
                v.x = acc[mt][nt][half * 2 + 0] + b0;
                v.y = acc[mt][nt][half * 2 + 1] + b1;
                if (QKV) {
                    const int bb = rr >> 11;
                    const int ss = rr & (Sn - 1);
                    const int hh = c >> 6;      // c < 1024 within the third
                    const int dd = c & (HDn - 1);
                    *(float2*)&Y[(size_t)((bb * Hn + hh) * Sn + ss) * HDn + dd] = v;
                } else {
                    *(float2*)&Y[(size_t)rr * Dn + c] = v;
                }
            }
        }
    }
}

// ===========================================================================
// Flash attention on mma.sync tf32. BQ=BK=64, HD=64. 128 threads = 4 warps,
// each warp owns 16 query rows. (unchanged from R9 — 255us measured)
// ===========================================================================
#define ASTR 76
#define FA_SMEM ((4 * 64 * ASTR + 64) * 4)   // 78080 B

__global__ void __launch_bounds__(128) flash_attn_mma(const float* __restrict__ qh,
                                                      const float* __restrict__ kh,
                                                      const float* __restrict__ vh,
                                                      const int* __restrict__ pad,
                                                      float* __restrict__ ctx)
{
    extern __shared__ uint32_t sm[];
    uint32_t* Qs = sm;                 // [query][d]   tf32, row stride 76
    uint32_t* Ks = Qs + 64 * ASTR;     // [key][d]     tf32 (natural)
    uint32_t* Vs = Ks + 64 * ASTR;     // [key][d]     tf32 (natural)
    uint32_t* Ps = Vs + 64 * ASTR;     // [query][key] tf32
    float*    PM = (float*)(Ps + 64 * ASTR);   // [64] pad flags

    const int t  = threadIdx.x;
    const int w  = t >> 5;
    const int ln = t & 31;
    const int g  = ln >> 2;      // 0..7
    const int q  = ln & 3;       // 0..3
    const int qt = blockIdx.x;
    const int h  = blockIdx.y;
    const int b  = blockIdx.z;
    const int q0 = qt * 64;
    const int wq = w * 16;

    const float* qb = qh + (size_t)((b * Hn + h) * Sn + q0) * HDn;
    const float* kb = kh + (size_t)((b * Hn + h) * Sn) * HDn;
    const float* vb = vh + (size_t)((b * Hn + h) * Sn) * HDn;

    // Load Q tile (pre-scaled by 1/sqrt(HD)=0.125, tf32-rounded)
#pragma unroll
    for (int i = 0; i < 8; i++) {
        const int cc  = t + 128 * i;       // 0..1023 float4 chunks
        const int row = cc >> 4;
        const int c4  = cc & 15;
        float4 v = *(const float4*)&qb[row * HDn + c4 * 4];
        uint4 u;
        u.x = cvt_tf32(v.x * 0.125f);
        u.y = cvt_tf32(v.y * 0.125f);
        u.z = cvt_tf32(v.z * 0.125f);
        u.w = cvt_tf32(v.w * 0.125f);
        *(uint4*)&Qs[row * ASTR + c4 * 4] = u;
    }

    float o[8][4];
#pragma unroll
    for (int dt = 0; dt < 8; dt++)
#pragma unroll
        for (int r = 0; r < 4; r++) o[dt][r] = 0.f;
    float mrow[2] = {-1e30f, -1e30f};
    float lrow[2] = {0.f, 0.f};

    const int r_lo = q0 + wq + g;
    const int r_hi = r_lo + 8;

    for (int kt = 0; kt <= qt; kt++) {
        const int k0 = kt * 64;
        __syncthreads();   // Ks/Vs reuse guard (also covers Qs on iter 0)

        // K and V tiles, natural [key][d] layout, vec4 stores
#pragma unroll
        for (int i = 0; i < 8; i++) {
            const int cc  = t + 128 * i;
            const int row = cc >> 4;
            const int c4  = cc & 15;
            float4 kv = *(const float4*)&kb[(size_t)(k0 + row) * HDn + c4 * 4];
            uint4 uk;
            uk.x = cvt_tf32(kv.x); uk.y = cvt_tf32(kv.y);
            uk.z = cvt_tf32(kv.z); uk.w = cvt_tf32(kv.w);
            *(uint4*)&Ks[row * ASTR + c4 * 4] = uk;
            float4 vv = *(const float4*)&vb[(size_t)(k0 + row) * HDn + c4 * 4];
            uint4 uv;
            uv.x = cvt_tf32(vv.x); uv.y = cvt_tf32(vv.y);
            uv.z = cvt_tf32(vv.z); uv.w = cvt_tf32(vv.w);
            *(uint4*)&Vs[row * ASTR + c4 * 4] = uv;
        }
        if (t < 64) PM[t] = (pad[b * Sn + k0 + t] != 0) ? 1.f : 0.f;
        __syncthreads();

        // ---- S = Q K^T  (scores, pre-scaled) ----
        float sv[8][4];
#pragma unroll
        for (int nt = 0; nt < 8; nt++)
#pragma unroll
            for (int r = 0; r < 4; r++) sv[nt][r] = 0.f;

#pragma unroll
        for (int kk = 0; kk < 8; kk++) {
            const int kb8 = kk * 8;
            uint32_t a[4];
            a[0] = Qs[(wq + g)     * ASTR + kb8 + q];
            a[1] = Qs[(wq + g + 8) * ASTR + kb8 + q];
            a[2] = Qs[(wq + g)     * ASTR + kb8 + q + 4];
            a[3] = Qs[(wq + g + 8) * ASTR + kb8 + q + 4];
#pragma unroll
            for (int nt = 0; nt < 8; nt++) {
                const int n = nt * 8 + g;
                const uint32_t b0 = Ks[n * ASTR + kb8 + q];      // K[n][k]
                const uint32_t b1 = Ks[n * ASTR + kb8 + q + 4];
                mma_tf32(sv[nt], a, b0, b1);
            }
        }

        // ---- mask (replace semantics, same as reference) ----
        const bool diag = (kt == qt);
#pragma unroll
        for (int nt = 0; nt < 8; nt++) {
            const int kx0 = nt * 8 + 2 * q;
            const bool pm0 = PM[kx0] != 0.f;
            const bool pm1 = PM[kx0 + 1] != 0.f;
            const int kg0 = k0 + kx0, kg1 = kg0 + 1;
            if (pm0 || (diag && kg0 > r_lo)) sv[nt][0] = NEGV;
            if (pm1 || (diag && kg1 > r_lo)) sv[nt][1] = NEGV;
            if (pm0 || (diag && kg0 > r_hi)) sv[nt][2] = NEGV;
            if (pm1 || (diag && kg1 > r_hi)) sv[nt][3] = NEGV;
        }

        // ---- online softmax (rows live in lane quads) ----
#pragma unroll
        for (int half = 0; half < 2; half++) {
            const int ci = half * 2;
            float tm = -1e30f;
#pragma unroll
            for (int nt = 0; nt < 8; nt++)
                tm = fmaxf(tm, fmaxf(sv[nt][ci], sv[nt][ci + 1]));
            tm = fmaxf(tm, __shfl_xor_sync(0xffffffffu, tm, 1));
            tm = fmaxf(tm, __shfl_xor_sync(0xffffffffu, tm, 2));
            const float mnew = fmaxf(mrow[half], tm);
            const float sc = expf(mrow[half] - mnew);
            float rs = 0.f;
#pragma unroll
            for (int nt = 0; nt < 8; nt++) {
                const float p0 = expf(sv[nt][ci]     - mnew);
                const float p1 = expf(sv[nt][ci + 1] - mnew);
                sv[nt][ci] = p0; sv[nt][ci + 1] = p1;
                rs += p0 + p1;
            }
            rs += __shfl_xor_sync(0xffffffffu, rs, 1);
            rs += __shfl_xor_sync(0xffffffffu, rs, 2);
            lrow[half] = lrow[half] * sc + rs;
            mrow[half] = mnew;
#pragma unroll
            for (int dt = 0; dt < 8; dt++) {
                o[dt][ci]     *= sc;
                o[dt][ci + 1] *= sc;
            }
        }

        // ---- store P (warp-private rows), tf32 ----
#pragma unroll
        for (int nt = 0; nt < 8; nt++) {
            const int col = nt * 8 + 2 * q;
            uint2 plo, phi;
            plo.x = cvt_tf32(sv[nt][0]); plo.y = cvt_tf32(sv[nt][1]);
            phi.x = cvt_tf32(sv[nt][2]); phi.y = cvt_tf32(sv[nt][3]);
            *(uint2*)&Ps[(wq + g)     * ASTR + col] = plo;
            *(uint2*)&Ps[(wq + g + 8) * ASTR + col] = phi;
        }
        __syncwarp();

        // ---- O += P V ----
#pragma unroll
        for (int kk = 0; kk < 8; kk++) {
            const int kb8 = kk * 8;
            uint32_t a[4];
            a[0] = Ps[(wq + g)     * ASTR + kb8 + q];
            a[1] = Ps[(wq + g + 8) * ASTR + kb8 + q];
            a[2] = Ps[(wq + g)     * ASTR + kb8 + q + 4];
            a[3] = Ps[(wq + g + 8) * ASTR + kb8 + q + 4];
#pragma unroll
            for (int dt = 0; dt < 8; dt++) {
                const int n = dt * 8 + g;
                const uint32_t b0 = Vs[(kb8 + q)     * ASTR + n];  // V[k][n]
                const uint32_t b1 = Vs[(kb8 + q + 4) * ASTR + n];
                mma_tf32(o[dt], a, b0, b1);
            }
        }
    }

    // ---- normalize + write context [B,S,D] ----
    const float inv_lo = 1.f / lrow[0];
    const float inv_hi = 1.f / lrow[1];
#pragma unroll
    for (int dt = 0; dt < 8; dt++) {
        const int col = h * HDn + dt * 8 + 2 * q;
        float2 vlo, vhi;
        vlo.x = o[dt][0] * inv_lo; vlo.y = o[dt][1] * inv_lo;
        vhi.x = o[dt][2] * inv_hi; vhi.y = o[dt][3] * inv_hi;
        *(float2*)&ctx[(size_t)(b * Sn + r_lo) * Dn + col] = vlo;
        *(float2*)&ctx[(size_t)(b * Sn + r_hi) * Dn + col] = vhi;
    }
}

// ---------------------------------------------------------------------------
extern "C" void kernel_launch(void* const* d_in, const int* in_sizes, int n_in,
                              void* d_out, int out_size)
{
    const float* x    = (const float*)d_in[0];   // q input [B,S,D]
    const int*   pm   = (const int*)d_in[1];     // pad_mask [B,S] (int32)
    const float* Wq   = (const float*)d_in[2];
    const float* bq   = (const float*)d_in[3];
    const float* Wk   = (const float*)d_in[4];
    const float* bk   = (const float*)d_in[5];
    const float* Wv   = (const float*)d_in[6];
    const float* bv   = (const float*)d_in[7];
    const float* Wo   = (const float*)d_in[8];
    const float* bo   = (const float*)d_in[9];
    float* out = (float*)d_out;

    float *qh, *kh, *vh, *ctx;
    cudaGetSymbolAddress((void**)&qh,  g_qh);
    cudaGetSymbolAddress((void**)&kh,  g_kh);
    cudaGetSymbolAddress((void**)&vh,  g_vh);
    cudaGetSymbolAddress((void**)&ctx, g_ctx);

    cudaFuncSetAttribute(flash_attn_mma, cudaFuncAttributeMaxDynamicSharedMemorySize,
                         FA_SMEM);

    // Fused Q/K/V projections: grid.x = 3 * (1024/BN) = 24
    const dim3 qkv_grid(24, (Bn * Sn) / BM);     // (24, 32) = 768 CTAs
    gemm_h<1><<<qkv_grid, 256, GEMM_SMEM>>>(x, Wq, Wk, Wv, bq, bk, bv, qh, kh, vh);

    dim3 agrid(Sn / 64, Hn, Bn);  // (32, 16, 2)
    flash_attn_mma<<<agrid, 128, FA_SMEM>>>(qh, kh, vh, pm, ctx);

    const dim3 o_grid(Dn / BN, (Bn * Sn) / BM);  // (8, 32)
    gemm_h<0><<<o_grid, 256, GEMM_SMEM>>>(ctx, Wo, nullptr, nullptr,
                                          bo, nullptr, nullptr,
                                          out, nullptr, nullptr);
}

// round 11
// speedup vs baseline: 4.0510x; 1.1742x over previous
#include <cuda_runtime.h>
#include <cuda_fp16.h>
#include <math.h>
#include <cstdint>

#define Bn 2
#define Sn 2048
#define Dn 1024
#define Hn 16
#define HDn 64
#define NEGV -1.0e9f

// Scratch (device globals: no allocations allowed)
__device__ float g_qh[Bn*Hn*Sn*HDn];   // [B,H,S,HD]
__device__ float g_kh[Bn*Hn*Sn*HDn];
__device__ float g_vh[Bn*Hn*Sn*HDn];
__device__ float g_ctx[Bn*Sn*Dn];      // [B,S,D] context before Wo

// fp16 m16n8k16 mma: same fragment index structure as verified tf32 m16n8k8
// with k replaced by k-pairs (each b32 = 2 adjacent k halves).
__device__ __forceinline__ void mma_f16(float* c, const uint32_t* a,
                                        uint32_t b0, uint32_t b1) {
    asm volatile(
        "mma.sync.aligned.m16n8k16.row.col.f32.f16.f16.f32 "
        "{%0,%1,%2,%3}, {%4,%5,%6,%7}, {%8,%9}, {%0,%1,%2,%3};"
        : "+f"(c[0]), "+f"(c[1]), "+f"(c[2]), "+f"(c[3])
        : "r"(a[0]), "r"(a[1]), "r"(a[2]), "r"(a[3]), "r"(b0), "r"(b1));
}

__device__ __forceinline__ uint32_t pack_h2(float x, float y) {
    __half2 h = __floats2half2_rn(x, y);
    return *reinterpret_cast<uint32_t*>(&h);
}

// ===========================================================================
// fp16 warp-MMA GEMM:  Y[n,m] = X[n,:] . W[m,:] + bias[m]   (torch Linear NT)
// BM=128, BN=128, BK=32, 256 threads = 8 warps (4x2), warp tile 32x64.
// (unchanged from R10 — QKV fused 163us measured)
// ===========================================================================
#define BM 128
#define BN 128
#define BKH 32
#define NPAIR (BKH / 2)
#define PKM 136
#define NSTAGES (Dn / BKH)
#define BUF_WORDS (NPAIR * PKM)          // 2176
#define GEMM_SMEM (4 * BUF_WORDS * 4)    // 34816 B

__device__ __forceinline__ int swidx(int p, int m) {
    return p * PKM + (m ^ (((p >> 2) & 7) << 2));
}

template<int QKV>
__global__ void __launch_bounds__(256) gemm_h(const float* __restrict__ X,
                                              const float* __restrict__ W0,
                                              const float* __restrict__ W1,
                                              const float* __restrict__ W2,
                                              const float* __restrict__ bias0,
                                              const float* __restrict__ bias1,
                                              const float* __restrict__ bias2,
                                              float* __restrict__ Y0,
                                              float* __restrict__ Y1,
                                              float* __restrict__ Y2)
{
    extern __shared__ uint32_t smem[];
    uint32_t* sA = smem;
    uint32_t* sB = smem + 2 * BUF_WORDS;

    const int t  = threadIdx.x;
    const int w  = t >> 5;
    const int ln = t & 31;
    const int g  = ln >> 2;
    const int q  = ln & 3;
    const int wm = (w & 3) * 32;
    const int wn = (w >> 2) * 64;
    const int rowBase = blockIdx.y * BM;

    int which = 0, colW = blockIdx.x * BN;
    if (QKV) { which = blockIdx.x >> 3; colW = (blockIdx.x & 7) * BN; }
    const float* W    = (which == 0) ? W0 : (which == 1) ? W1 : W2;
    const float* bias = (which == 0) ? bias0 : (which == 1) ? bias1 : bias2;
    float*       Y    = (which == 0) ? Y0 : (which == 1) ? Y1 : Y2;

    float acc[2][8][4];
#pragma unroll
    for (int mt = 0; mt < 2; mt++)
#pragma unroll
        for (int nt = 0; nt < 8; nt++)
#pragma unroll
            for (int r = 0; r < 4; r++) acc[mt][nt][r] = 0.f;

    float4 ra[4], rb[4];

    auto ldg = [&](int s) {
        const int k0 = s * BKH;
#pragma unroll
        for (int i = 0; i < 4; i++) {
            const int e = t + 256 * i;
            const int m = e >> 3, kq = e & 7;
            ra[i] = *(const float4*)&X[(size_t)(rowBase + m) * Dn + k0 + kq * 4];
            rb[i] = *(const float4*)&W[(size_t)(colW + m) * Dn + k0 + kq * 4];
        }
    };

    auto sts = [&](int buf) {
        uint32_t* a = sA + buf * BUF_WORDS;
        uint32_t* b = sB + buf * BUF_WORDS;
#pragma unroll
        for (int i = 0; i < 4; i++) {
            const int e = t + 256 * i;
            const int m = e >> 3, kq = e & 7;
            a[swidx(2 * kq + 0, m)] = pack_h2(ra[i].x, ra[i].y);
            a[swidx(2 * kq + 1, m)] = pack_h2(ra[i].z, ra[i].w);
            b[swidx(2 * kq + 0, m)] = pack_h2(rb[i].x, rb[i].y);
            b[swidx(2 * kq + 1, m)] = pack_h2(rb[i].z, rb[i].w);
        }
    };

    auto comp = [&](int buf) {
        const uint32_t* a = sA + buf * BUF_WORDS;
        const uint32_t* b = sB + buf * BUF_WORDS;
#pragma unroll
        for (int kk = 0; kk < 2; kk++) {
            const int kbp = kk * 8;
            uint32_t af[2][4];
#pragma unroll
            for (int mt = 0; mt < 2; mt++) {
                const int m = wm + mt * 16 + g;
                af[mt][0] = a[swidx(kbp + q,     m)];
                af[mt][1] = a[swidx(kbp + q,     m + 8)];
                af[mt][2] = a[swidx(kbp + q + 4, m)];
                af[mt][3] = a[swidx(kbp + q + 4, m + 8)];
            }
#pragma unroll
            for (int nt = 0; nt < 8; nt++) {
                const int n = wn + nt * 8 + g;
                const uint32_t b0 = b[swidx(kbp + q,     n)];
                const uint32_t b1 = b[swidx(kbp + q + 4, n)];
                mma_f16(acc[0][nt], af[0], b0, b1);
                mma_f16(acc[1][nt], af[1], b0, b1);
            }
        }
    };

    ldg(0);
    sts(0);
    __syncthreads();
    for (int s = 0; s < NSTAGES; s++) {
        if (s + 1 < NSTAGES) ldg(s + 1);
        comp(s & 1);
        if (s + 1 < NSTAGES) {
            __syncthreads();
            sts((s + 1) & 1);
            __syncthreads();
        }
    }

#pragma unroll
    for (int nt = 0; nt < 8; nt++) {
        const int c = colW + wn + nt * 8 + 2 * q;
        const float b0 = bias[c], b1 = bias[c + 1];
#pragma unroll
        for (int mt = 0; mt < 2; mt++) {
            const int r0 = rowBase + wm + mt * 16 + g;
#pragma unroll
            for (int half = 0; half < 2; half++) {
                const int rr = r0 + half * 8;
                float2 v;
                v.x = acc[mt][nt][half * 2 + 0] + b0;
                v.y = acc[mt][nt][half * 2 + 1] + b1;
                if (QKV) {
                    const int bb = rr >> 11;
                    const int ss = rr & (Sn - 1);
                    const int hh = c >> 6;
                    const int dd = c & (HDn - 1);
                    *(float2*)&Y[(size_t)((bb * Hn + hh) * Sn + ss) * HDn + dd] = v;
                } else {
                    *(float2*)&Y[(size_t)rr * Dn + c] = v;
                }
            }
        }
    }
}

// ===========================================================================
// Flash attention on fp16 mma.sync m16n8k16. BQ=BK=64, HD=64.
// 128 threads = 4 warps, each owns 16 query rows. Pair-stride 36 smem.
// V stored transposed [d][kpair] with j ^ ((d>>3)&3) swizzle — conflict-free
// for both the transposing stores and the B-fragment loads.
// ===========================================================================
#define PSTR 36
#define FA_SMEM ((4 * 64 * PSTR + 64) * 4)   // 37120 B

__global__ void __launch_bounds__(128) flash_attn_h(const float* __restrict__ qh,
                                                    const float* __restrict__ kh,
                                                    const float* __restrict__ vh,
                                                    const int* __restrict__ pad,
                                                    float* __restrict__ ctx)
{
    extern __shared__ uint32_t sm[];
    uint32_t* Qs = sm;                 // [query][32 kpairs] half2, stride 36
    uint32_t* Ks = Qs + 64 * PSTR;     // [key][32 kpairs]
    uint32_t* Vt = Ks + 64 * PSTR;     // [d][32 kpairs] (transposed, swizzled)
    uint32_t* Ps = Vt + 64 * PSTR;     // [query][32 kpairs]
    float*    PM = (float*)(Ps + 64 * PSTR);   // [64] pad flags

    const int t  = threadIdx.x;
    const int w  = t >> 5;
    const int ln = t & 31;
    const int g  = ln >> 2;      // 0..7
    const int q  = ln & 3;       // 0..3
    const int qt = blockIdx.x;
    const int h  = blockIdx.y;
    const int b  = blockIdx.z;
    const int q0 = qt * 64;
    const int wq = w * 16;

    const float* qb = qh + (size_t)((b * Hn + h) * Sn + q0) * HDn;
    const float* kb = kh + (size_t)((b * Hn + h) * Sn) * HDn;
    const float* vb = vh + (size_t)((b * Hn + h) * Sn) * HDn;

    // Load Q tile (pre-scaled by 1/sqrt(HD)=0.125), packed to half2 pairs
#pragma unroll
    for (int i = 0; i < 8; i++) {
        const int cc  = t + 128 * i;       // 1024 float4 chunks
        const int row = cc >> 4;
        const int c4  = cc & 15;
        float4 v = *(const float4*)&qb[row * HDn + c4 * 4];
        uint2 u;
        u.x = pack_h2(v.x * 0.125f, v.y * 0.125f);
        u.y = pack_h2(v.z * 0.125f, v.w * 0.125f);
        *(uint2*)&Qs[row * PSTR + 2 * c4] = u;
    }

    float o[8][4];
#pragma unroll
    for (int dt = 0; dt < 8; dt++)
#pragma unroll
        for (int r = 0; r < 4; r++) o[dt][r] = 0.f;
    float mrow[2] = {-1e30f, -1e30f};
    float lrow[2] = {0.f, 0.f};

    const int r_lo = q0 + wq + g;
    const int r_hi = r_lo + 8;

    for (int kt = 0; kt <= qt; kt++) {
        const int k0 = kt * 64;
        __syncthreads();   // Ks/Vt reuse guard (also covers Qs on iter 0)

        // K tile: natural [key][kpair]
#pragma unroll
        for (int i = 0; i < 8; i++) {
            const int cc  = t + 128 * i;
            const int row = cc >> 4;
            const int c4  = cc & 15;
            float4 kv = *(const float4*)&kb[(size_t)(k0 + row) * HDn + c4 * 4];
            uint2 u;
            u.x = pack_h2(kv.x, kv.y);
            u.y = pack_h2(kv.z, kv.w);
            *(uint2*)&Ks[row * PSTR + 2 * c4] = u;
        }
        // V transposed: Vt[d][jpair] = {V[k0+2j][d], V[k0+2j+1][d]}
#pragma unroll
        for (int i = 0; i < 16; i++) {
            const int idx = t + 128 * i;   // 2048 half2 words
            const int d = idx & 63;
            const int j = idx >> 6;
            const float v0 = vb[(size_t)(k0 + 2 * j) * HDn + d];
            const float v1 = vb[(size_t)(k0 + 2 * j + 1) * HDn + d];
            Vt[d * PSTR + (j ^ ((d >> 3) & 3))] = pack_h2(v0, v1);
        }
        if (t < 64) PM[t] = (pad[b * Sn + k0 + t] != 0) ? 1.f : 0.f;
        __syncthreads();

        // ---- S = Q K^T  (4 x k16 steps) ----
        float sv[8][4];
#pragma unroll
        for (int nt = 0; nt < 8; nt++)
#pragma unroll
            for (int r = 0; r < 4; r++) sv[nt][r] = 0.f;

#pragma unroll
        for (int kk = 0; kk < 4; kk++) {
            const int kbp = kk * 8;
            uint32_t a[4];
            a[0] = Qs[(wq + g)     * PSTR + kbp + q];
            a[1] = Qs[(wq + g + 8) * PSTR + kbp + q];
            a[2] = Qs[(wq + g)     * PSTR + kbp + q + 4];
            a[3] = Qs[(wq + g + 8) * PSTR + kbp + q + 4];
#pragma unroll
            for (int nt = 0; nt < 8; nt++) {
                const int n = nt * 8 + g;
                const uint32_t b0 = Ks[n * PSTR + kbp + q];
                const uint32_t b1 = Ks[n * PSTR + kbp + q + 4];
                mma_f16(sv[nt], a, b0, b1);
            }
        }

        // ---- mask (replace semantics, same as reference) ----
        const bool diag = (kt == qt);
#pragma unroll
        for (int nt = 0; nt < 8; nt++) {
            const int kx0 = nt * 8 + 2 * q;
            const bool pm0 = PM[kx0] != 0.f;
            const bool pm1 = PM[kx0 + 1] != 0.f;
            const int kg0 = k0 + kx0, kg1 = kg0 + 1;
            if (pm0 || (diag && kg0 > r_lo)) sv[nt][0] = NEGV;
            if (pm1 || (diag && kg1 > r_lo)) sv[nt][1] = NEGV;
            if (pm0 || (diag && kg0 > r_hi)) sv[nt][2] = NEGV;
            if (pm1 || (diag && kg1 > r_hi)) sv[nt][3] = NEGV;
        }

        // ---- online softmax (rows live in lane quads) ----
#pragma unroll
        for (int half = 0; half < 2; half++) {
            const int ci = half * 2;
            float tm = -1e30f;
#pragma unroll
            for (int nt = 0; nt < 8; nt++)
                tm = fmaxf(tm, fmaxf(sv[nt][ci], sv[nt][ci + 1]));
            tm = fmaxf(tm, __shfl_xor_sync(0xffffffffu, tm, 1));
            tm = fmaxf(tm, __shfl_xor_sync(0xffffffffu, tm, 2));
            const float mnew = fmaxf(mrow[half], tm);
            const float sc = __expf(mrow[half] - mnew);
            float rs = 0.f;
#pragma unroll
            for (int nt = 0; nt < 8; nt++) {
                const float p0 = __expf(sv[nt][ci]     - mnew);
                const float p1 = __expf(sv[nt][ci + 1] - mnew);
                sv[nt][ci] = p0; sv[nt][ci + 1] = p1;
                rs += p0 + p1;
            }
            rs += __shfl_xor_sync(0xffffffffu, rs, 1);
            rs += __shfl_xor_sync(0xffffffffu, rs, 2);
            lrow[half] = lrow[half] * sc + rs;
            mrow[half] = mnew;
#pragma unroll
            for (int dt = 0; dt < 8; dt++) {
                o[dt][ci]     *= sc;
                o[dt][ci + 1] *= sc;
            }
        }

        // ---- store P as half2 pairs: cols (8nt+2q, +1) = pair 4nt+q ----
#pragma unroll
        for (int nt = 0; nt < 8; nt++) {
            Ps[(wq + g)     * PSTR + 4 * nt + q] = pack_h2(sv[nt][0], sv[nt][1]);
            Ps[(wq + g + 8) * PSTR + 4 * nt + q] = pack_h2(sv[nt][2], sv[nt][3]);
        }
        __syncwarp();

        // ---- O += P V  (4 x k16 steps over key pairs) ----
#pragma unroll
        for (int kk = 0; kk < 4; kk++) {
            const int kbp = kk * 8;
            uint32_t a[4];
            a[0] = Ps[(wq + g)     * PSTR + kbp + q];
            a[1] = Ps[(wq + g + 8) * PSTR + kbp + q];
            a[2] = Ps[(wq + g)     * PSTR + kbp + q + 4];
            a[3] = Ps[(wq + g + 8) * PSTR + kbp + q + 4];
#pragma unroll
            for (int dt = 0; dt < 8; dt++) {
                const int n = dt * 8 + g;
                const int sw = (n >> 3) & 3;
                const uint32_t b0 = Vt[n * PSTR + ((kbp + q)     ^ sw)];
                const uint32_t b1 = Vt[n * PSTR + ((kbp + q + 4) ^ sw)];
                mma_f16(o[dt], a, b0, b1);
            }
        }
    }

    // ---- normalize + write context [B,S,D] ----
    const float inv_lo = 1.f / lrow[0];
    const float inv_hi = 1.f / lrow[1];
#pragma unroll
    for (int dt = 0; dt < 8; dt++) {
        const int col = h * HDn + dt * 8 + 2 * q;
        float2 vlo, vhi;
        vlo.x = o[dt][0] * inv_lo; vlo.y = o[dt][1] * inv_lo;
        vhi.x = o[dt][2] * inv_hi; vhi.y = o[dt][3] * inv_hi;
        *(float2*)&ctx[(size_t)(b * Sn + r_lo) * Dn + col] = vlo;
        *(float2*)&ctx[(size_t)(b * Sn + r_hi) * Dn + col] = vhi;
    }
}

// ---------------------------------------------------------------------------
extern "C" void kernel_launch(void* const* d_in, const int* in_sizes, int n_in,
                              void* d_out, int out_size)
{
    const float* x    = (const float*)d_in[0];   // q input [B,S,D]
    const int*   pm   = (const int*)d_in[1];     // pad_mask [B,S] (int32)
    const float* Wq   = (const float*)d_in[2];
    const float* bq   = (const float*)d_in[3];
    const float* Wk   = (const float*)d_in[4];
    const float* bk   = (const float*)d_in[5];
    const float* Wv   = (const float*)d_in[6];
    const float* bv   = (const float*)d_in[7];
    const float* Wo   = (const float*)d_in[8];
    const float* bo   = (const float*)d_in[9];
    float* out = (float*)d_out;

    float *qh, *kh, *vh, *ctx;
    cudaGetSymbolAddress((void**)&qh,  g_qh);
    cudaGetSymbolAddress((void**)&kh,  g_kh);
    cudaGetSymbolAddress((void**)&vh,  g_vh);
    cudaGetSymbolAddress((void**)&ctx, g_ctx);

    cudaFuncSetAttribute(flash_attn_h, cudaFuncAttributeMaxDynamicSharedMemorySize,
                         FA_SMEM);

    // Fused Q/K/V projections: grid.x = 3 * (1024/BN) = 24
    const dim3 qkv_grid(24, (Bn * Sn) / BM);     // (24, 32) = 768 CTAs
    gemm_h<1><<<qkv_grid, 256, GEMM_SMEM>>>(x, Wq, Wk, Wv, bq, bk, bv, qh, kh, vh);

    dim3 agrid(Sn / 64, Hn, Bn);  // (32, 16, 2)
    flash_attn_h<<<agrid, 128, FA_SMEM>>>(qh, kh, vh, pm, ctx);

    const dim3 o_grid(Dn / BN, (Bn * Sn) / BM);  // (8, 32)
    gemm_h<0><<<o_grid, 256, GEMM_SMEM>>>(ctx, Wo, nullptr, nullptr,
                                          bo, nullptr, nullptr,
                                          out, nullptr, nullptr);
}

// round 12
// speedup vs baseline: 5.7690x; 1.4241x over previous
#include <cuda_runtime.h>
#include <cuda_fp16.h>
#include <math.h>
#include <cstdint>

#define Bn 2
#define Sn 2048
#define Dn 1024
#define Hn 16
#define HDn 64
#define NEGV -1.0e9f

// Scratch (device globals: no allocations allowed)
__device__ __half g_xh[Bn*Sn*Dn];        // X in half
__device__ __half g_wh[4*Dn*Dn];         // Wq,Wk,Wv,Wo in half
__device__ __half g_qh[Bn*Hn*Sn*HDn];    // [B,H,S,HD] (pre-scaled by 0.125)
__device__ __half g_kh[Bn*Hn*Sn*HDn];
__device__ __half g_vh[Bn*Hn*Sn*HDn];
__device__ __half g_ctx[Bn*Sn*Dn];       // [B,S,D] context before Wo

__device__ __forceinline__ void mma_f16(float* c, const uint32_t* a,
                                        uint32_t b0, uint32_t b1) {
    asm volatile(
        "mma.sync.aligned.m16n8k16.row.col.f32.f16.f16.f32 "
        "{%0,%1,%2,%3}, {%4,%5,%6,%7}, {%8,%9}, {%0,%1,%2,%3};"
        : "+f"(c[0]), "+f"(c[1]), "+f"(c[2]), "+f"(c[3])
        : "r"(a[0]), "r"(a[1]), "r"(a[2]), "r"(a[3]), "r"(b0), "r"(b1));
}

__device__ __forceinline__ uint32_t pack_h2(float x, float y) {
    __half2 h = __floats2half2_rn(x, y);
    return *reinterpret_cast<uint32_t*>(&h);
}

__device__ __forceinline__ uint32_t smem_u32(const void* p) {
    uint32_t a;
    asm("{ .reg .u64 t; cvta.to.shared.u64 t, %1; cvt.u32.u64 %0, t; }"
        : "=r"(a) : "l"(p));
    return a;
}

#define CP16(dst_u32, src_ptr)                                               \
    asm volatile("cp.async.cg.shared.global [%0], [%1], 16;"                 \
                 :: "r"(dst_u32), "l"(src_ptr))
#define CP_COMMIT() asm volatile("cp.async.commit_group;" ::: "memory")
#define CP_WAIT(N)  asm volatile("cp.async.wait_group %0;" :: "n"(N) : "memory")

// ===========================================================================
// Pre-conversion: X (4M floats) + 4 weight matrices (4M floats) -> half.
// One float4 per thread -> uint2 (4 halves). 2^21 float4s total.
// ===========================================================================
__global__ void __launch_bounds__(256) cvt_inputs(const float4* __restrict__ X,
                                                  const float4* __restrict__ Wq,
                                                  const float4* __restrict__ Wk,
                                                  const float4* __restrict__ Wv,
                                                  const float4* __restrict__ Wo)
{
    const int idx = blockIdx.x * 256 + threadIdx.x;   // 0 .. 2^21-1
    const int XQ = (Bn * Sn * Dn) / 4;                // 2^20
    float4 v;
    uint2* dst;
    if (idx < XQ) {
        v = X[idx];
        dst = reinterpret_cast<uint2*>(g_xh) + idx;
    } else {
        const int j = idx - XQ;                       // 0 .. 2^20-1
        const int which = j >> 18;                    // 256K float4 per W
        const int off = j & ((1 << 18) - 1);
        const float4* W = (which == 0) ? Wq : (which == 1) ? Wk
                        : (which == 2) ? Wv : Wo;
        v = W[off];
        dst = reinterpret_cast<uint2*>(g_wh) + (which << 18) + off;
    }
    uint2 u;
    u.x = pack_h2(v.x, v.y);
    u.y = pack_h2(v.z, v.w);
    *dst = u;
}

// ===========================================================================
// fp16 cp.async GEMM:  Y[n,m] = Xh[n,:] . Wh[m,:] + bias[m]
// BM=128, BN=128, BK=64 halves (128B rows -> SW128 chunk^(m&7) swizzle).
// 256 threads = 8 warps (4x2), warp tile 32x64, double-buffered cp.async.
// QKV=1: 3 fused projections, half output in [B,H,S,HD] (Q scaled 0.125).
// QKV=0: Wo — reads half ctx, writes fp32 row-major.
// ===========================================================================
#define BM 128
#define BN 128
#define BKH2 64
#define GSTAGES (Dn / BKH2)              // 16
#define TILE_W 4096                       // words per 128x64h tile (16 KB)
#define GEMM_SMEM (4 * TILE_W * 4)        // 65536 B

template<int QKV>
__global__ void __launch_bounds__(256, 2)
gemm_cp(const __half* __restrict__ Xh,
        const __half* __restrict__ Wh,       // base of (3 or 1) weight blocks
        const float* __restrict__ bias0,
        const float* __restrict__ bias1,
        const float* __restrict__ bias2,
        __half* __restrict__ Y0,
        __half* __restrict__ Y1,
        __half* __restrict__ Y2,
        float* __restrict__ Yf)
{
    extern __shared__ uint32_t smem[];
    const uint32_t smem_b = smem_u32(smem);

    const int t  = threadIdx.x;
    const int w  = t >> 5;
    const int ln = t & 31;
    const int g  = ln >> 2;
    const int q  = ln & 3;
    const int wm = (w & 3) * 32;
    const int wn = (w >> 2) * 64;
    const int rowBase = blockIdx.y * BM;

    int which = 0, colW = blockIdx.x * BN;
    if (QKV) { which = blockIdx.x >> 3; colW = (blockIdx.x & 7) * BN; }
    const __half* W    = Wh + (size_t)which * Dn * Dn;
    const float* bias  = (which == 0) ? bias0 : (which == 1) ? bias1 : bias2;
    __half*      Y     = (which == 0) ? Y0 : (which == 1) ? Y1 : Y2;
    const float  scale = (QKV && which == 0) ? 0.125f : 1.0f;

    float acc[2][8][4];
#pragma unroll
    for (int mt = 0; mt < 2; mt++)
#pragma unroll
        for (int nt = 0; nt < 8; nt++)
#pragma unroll
            for (int r = 0; r < 4; r++) acc[mt][nt][r] = 0.f;

    // cp.async one stage: A(16KB) + B(16KB), 8 x 16B per thread
    const int lm = t >> 3;          // not used directly; per-chunk below
    (void)lm;
    auto issue = [&](int s) {
        const int buf = s & 1;
        const int k0 = s * BKH2;
        const uint32_t aB = smem_b + (buf * 2 * TILE_W) * 4;
        const uint32_t bB = aB + TILE_W * 4;
#pragma unroll
        for (int i = 0; i < 4; i++) {
            const int e = t + 256 * i;       // 1024 chunks
            const int m = e >> 3, c = e & 7;
            const uint32_t swoff = (uint32_t)(m * 128 + ((c ^ (m & 7)) << 4));
            CP16(aB + swoff, &Xh[(size_t)(rowBase + m) * Dn + k0 + c * 8]);
            CP16(bB + swoff, &W[(size_t)(colW + m) * Dn + k0 + c * 8]);
        }
        CP_COMMIT();
    };

    auto comp = [&](int buf) {
        const uint32_t* A = smem + buf * 2 * TILE_W;
        const uint32_t* B = A + TILE_W;
#pragma unroll
        for (int kk = 0; kk < 4; kk++) {
            const int c0 = 2 * kk, c1 = 2 * kk + 1;
            uint32_t af[2][4];
#pragma unroll
            for (int mt = 0; mt < 2; mt++) {
                const int m = wm + mt * 16 + g;       // m&7 == g
                af[mt][0] = A[m * 32 + ((c0 ^ g) << 2) + q];
                af[mt][1] = A[(m + 8) * 32 + ((c0 ^ g) << 2) + q];
                af[mt][2] = A[m * 32 + ((c1 ^ g) << 2) + q];
                af[mt][3] = A[(m + 8) * 32 + ((c1 ^ g) << 2) + q];
            }
#pragma unroll
            for (int nt = 0; nt < 8; nt++) {
                const int n = wn + nt * 8 + g;        // n&7 == g
                const uint32_t b0 = B[n * 32 + ((c0 ^ g) << 2) + q];
                const uint32_t b1 = B[n * 32 + ((c1 ^ g) << 2) + q];
                mma_f16(acc[0][nt], af[0], b0, b1);
                mma_f16(acc[1][nt], af[1], b0, b1);
            }
        }
    };

    issue(0);
    issue(1);
    for (int s = 0; s < GSTAGES; s++) {
        if (s + 1 < GSTAGES) CP_WAIT(1); else CP_WAIT(0);
        __syncthreads();
        comp(s & 1);
        if (s + 2 < GSTAGES) {
            __syncthreads();          // finish reading buf before refill
            issue(s + 2);
        }
    }

    // Epilogue
#pragma unroll
    for (int nt = 0; nt < 8; nt++) {
        const int c = colW + wn + nt * 8 + 2 * q;
        const float b0 = bias[c], b1 = bias[c + 1];
#pragma unroll
        for (int mt = 0; mt < 2; mt++) {
            const int r0 = rowBase + wm + mt * 16 + g;
#pragma unroll
            for (int half = 0; half < 2; half++) {
                const int rr = r0 + half * 8;
                const float vx = (acc[mt][nt][half * 2 + 0] + b0) * scale;
                const float vy = (acc[mt][nt][half * 2 + 1] + b1) * scale;
                if (QKV) {
                    const int bb = rr >> 11;
                    const int ss = rr & (Sn - 1);
                    const int hh = c >> 6;
                    const int dd = c & (HDn - 1);
                    *(uint32_t*)&Y[(size_t)((bb * Hn + hh) * Sn + ss) * HDn + dd] =
                        pack_h2(vx, vy);
                } else {
                    float2 v; v.x = vx; v.y = vy;
                    *(float2*)&Yf[(size_t)rr * Dn + c] = v;
                }
            }
        }
    }
}

// ===========================================================================
// Flash attention, fp16 mma m16n8k16, half inputs. BQ=BK=64, HD=64.
// 128 threads = 4 warps, each owns 16 query rows. Pair-stride 36 smem.
// (structure verified R11 at ~145us; fills now pure half copies)
// ===========================================================================
#define PSTR 36
#define FA_SMEM ((4 * 64 * PSTR + 64) * 4)   // 37120 B

__global__ void __launch_bounds__(128) flash_attn_h(const __half* __restrict__ qh,
                                                    const __half* __restrict__ kh,
                                                    const __half* __restrict__ vh,
                                                    const int* __restrict__ pad,
                                                    __half* __restrict__ ctx)
{
    extern __shared__ uint32_t sm[];
    uint32_t* Qs = sm;                 // [query][32 kpairs], stride 36
    uint32_t* Ks = Qs + 64 * PSTR;
    uint32_t* Vt = Ks + 64 * PSTR;     // [d][32 kpairs] transposed + swizzled
    uint32_t* Ps = Vt + 64 * PSTR;
    float*    PM = (float*)(Ps + 64 * PSTR);

    const int t  = threadIdx.x;
    const int w  = t >> 5;
    const int ln = t & 31;
    const int g  = ln >> 2;
    const int q  = ln & 3;
    const int qt = blockIdx.x;
    const int h  = blockIdx.y;
    const int b  = blockIdx.z;
    const int q0 = qt * 64;
    const int wq = w * 16;

    const __half* qb = qh + (size_t)((b * Hn + h) * Sn + q0) * HDn;
    const __half* kb = kh + (size_t)((b * Hn + h) * Sn) * HDn;
    const __half* vb = vh + (size_t)((b * Hn + h) * Sn) * HDn;

    // Q tile: pure copy (already scaled + half). 512 uint4 chunks.
#pragma unroll
    for (int i = 0; i < 4; i++) {
        const int cc  = t + 128 * i;
        const int row = cc >> 3;
        const int c8  = cc & 7;
        uint4 u = *(const uint4*)&qb[row * HDn + c8 * 8];
        *(uint4*)&Qs[row * PSTR + c8 * 4] = u;
    }

    float o[8][4];
#pragma unroll
    for (int dt = 0; dt < 8; dt++)
#pragma unroll
        for (int r = 0; r < 4; r++) o[dt][r] = 0.f;
    float mrow[2] = {-1e30f, -1e30f};
    float lrow[2] = {0.f, 0.f};

    const int r_lo = q0 + wq + g;
    const int r_hi = r_lo + 8;

    for (int kt = 0; kt <= qt; kt++) {
        const int k0 = kt * 64;
        __syncthreads();

        // K tile copy
#pragma unroll
        for (int i = 0; i < 4; i++) {
            const int cc  = t + 128 * i;
            const int row = cc >> 3;
            const int c8  = cc & 7;
            uint4 u = *(const uint4*)&kb[(size_t)(k0 + row) * HDn + c8 * 8];
            *(uint4*)&Ks[row * PSTR + c8 * 4] = u;
        }
        // V transposed: Vt[d][jpair] = {V[k0+2j][d], V[k0+2j+1][d]}
#pragma unroll
        for (int i = 0; i < 16; i++) {
            const int idx = t + 128 * i;   // 2048 pair words
            const int d = idx & 63;
            const int j = idx >> 6;
            const uint32_t v0 = *(const uint16_t*)&vb[(size_t)(k0 + 2 * j) * HDn + d];
            const uint32_t v1 = *(const uint16_t*)&vb[(size_t)(k0 + 2 * j + 1) * HDn + d];
            Vt[d * PSTR + (j ^ ((d >> 3) & 3))] = v0 | (v1 << 16);
        }
        if (t < 64) PM[t] = (pad[b * Sn + k0 + t] != 0) ? 1.f : 0.f;
        __syncthreads();

        // ---- S = Q K^T ----
        float sv[8][4];
#pragma unroll
        for (int nt = 0; nt < 8; nt++)
#pragma unroll
            for (int r = 0; r < 4; r++) sv[nt][r] = 0.f;

#pragma unroll
        for (int kk = 0; kk < 4; kk++) {
            const int kbp = kk * 8;
            uint32_t a[4];
            a[0] = Qs[(wq + g)     * PSTR + kbp + q];
            a[1] = Qs[(wq + g + 8) * PSTR + kbp + q];
            a[2] = Qs[(wq + g)     * PSTR + kbp + q + 4];
            a[3] = Qs[(wq + g + 8) * PSTR + kbp + q + 4];
#pragma unroll
            for (int nt = 0; nt < 8; nt++) {
                const int n = nt * 8 + g;
                const uint32_t b0 = Ks[n * PSTR + kbp + q];
                const uint32_t b1 = Ks[n * PSTR + kbp + q + 4];
                mma_f16(sv[nt], a, b0, b1);
            }
        }

        // ---- mask ----
        const bool diag = (kt == qt);
#pragma unroll
        for (int nt = 0; nt < 8; nt++) {
            const int kx0 = nt * 8 + 2 * q;
            const bool pm0 = PM[kx0] != 0.f;
            const bool pm1 = PM[kx0 + 1] != 0.f;
            const int kg0 = k0 + kx0, kg1 = kg0 + 1;
            if (pm0 || (diag && kg0 > r_lo)) sv[nt][0] = NEGV;
            if (pm1 || (diag && kg1 > r_lo)) sv[nt][1] = NEGV;
            if (pm0 || (diag && kg0 > r_hi)) sv[nt][2] = NEGV;
            if (pm1 || (diag && kg1 > r_hi)) sv[nt][3] = NEGV;
        }

        // ---- online softmax ----
#pragma unroll
        for (int half = 0; half < 2; half++) {
            const int ci = half * 2;
            float tm = -1e30f;
#pragma unroll
            for (int nt = 0; nt < 8; nt++)
                tm = fmaxf(tm, fmaxf(sv[nt][ci], sv[nt][ci + 1]));
            tm = fmaxf(tm, __shfl_xor_sync(0xffffffffu, tm, 1));
            tm = fmaxf(tm, __shfl_xor_sync(0xffffffffu, tm, 2));
            const float mnew = fmaxf(mrow[half], tm);
            const float sc = __expf(mrow[half] - mnew);
            float rs = 0.f;
#pragma unroll
            for (int nt = 0; nt < 8; nt++) {
                const float p0 = __expf(sv[nt][ci]     - mnew);
                const float p1 = __expf(sv[nt][ci + 1] - mnew);
                sv[nt][ci] = p0; sv[nt][ci + 1] = p1;
                rs += p0 + p1;
            }
            rs += __shfl_xor_sync(0xffffffffu, rs, 1);
            rs += __shfl_xor_sync(0xffffffffu, rs, 2);
            lrow[half] = lrow[half] * sc + rs;
            mrow[half] = mnew;
#pragma unroll
            for (int dt = 0; dt < 8; dt++) {
                o[dt][ci]     *= sc;
                o[dt][ci + 1] *= sc;
            }
        }

        // ---- store P as pairs ----
#pragma unroll
        for (int nt = 0; nt < 8; nt++) {
            Ps[(wq + g)     * PSTR + 4 * nt + q] = pack_h2(sv[nt][0], sv[nt][1]);
            Ps[(wq + g + 8) * PSTR + 4 * nt + q] = pack_h2(sv[nt][2], sv[nt][3]);
        }
        __syncwarp();

        // ---- O += P V ----
#pragma unroll
        for (int kk = 0; kk < 4; kk++) {
            const int kbp = kk * 8;
            uint32_t a[4];
            a[0] = Ps[(wq + g)     * PSTR + kbp + q];
            a[1] = Ps[(wq + g + 8) * PSTR + kbp + q];
            a[2] = Ps[(wq + g)     * PSTR + kbp + q + 4];
            a[3] = Ps[(wq + g + 8) * PSTR + kbp + q + 4];
#pragma unroll
            for (int dt = 0; dt < 8; dt++) {
                const int n = dt * 8 + g;
                const int sw = (n >> 3) & 3;
                const uint32_t b0 = Vt[n * PSTR + ((kbp + q)     ^ sw)];
                const uint32_t b1 = Vt[n * PSTR + ((kbp + q + 4) ^ sw)];
                mma_f16(o[dt], a, b0, b1);
            }
        }
    }

    // ---- normalize + write half context ----
    const float inv_lo = 1.f / lrow[0];
    const float inv_hi = 1.f / lrow[1];
#pragma unroll
    for (int dt = 0; dt < 8; dt++) {
        const int col = h * HDn + dt * 8 + 2 * q;
        *(uint32_t*)&ctx[(size_t)(b * Sn + r_lo) * Dn + col] =
            pack_h2(o[dt][0] * inv_lo, o[dt][1] * inv_lo);
        *(uint32_t*)&ctx[(size_t)(b * Sn + r_hi) * Dn + col] =
            pack_h2(o[dt][2] * inv_hi, o[dt][3] * inv_hi);
    }
}

// ---------------------------------------------------------------------------
extern "C" void kernel_launch(void* const* d_in, const int* in_sizes, int n_in,
                              void* d_out, int out_size)
{
    const float* x    = (const float*)d_in[0];
    const int*   pm   = (const int*)d_in[1];
    const float* Wq   = (const float*)d_in[2];
    const float* bq   = (const float*)d_in[3];
    const float* Wk   = (const float*)d_in[4];
    const float* bk   = (const float*)d_in[5];
    const float* Wv   = (const float*)d_in[6];
    const float* bv   = (const float*)d_in[7];
    const float* Wo   = (const float*)d_in[8];
    const float* bo   = (const float*)d_in[9];
    float* out = (float*)d_out;

    __half *xh, *wh, *qh, *kh, *vh, *ctx;
    cudaGetSymbolAddress((void**)&xh,  g_xh);
    cudaGetSymbolAddress((void**)&wh,  g_wh);
    cudaGetSymbolAddress((void**)&qh,  g_qh);
    cudaGetSymbolAddress((void**)&kh,  g_kh);
    cudaGetSymbolAddress((void**)&vh,  g_vh);
    cudaGetSymbolAddress((void**)&ctx, g_ctx);

    cudaFuncSetAttribute(gemm_cp<1>, cudaFuncAttributeMaxDynamicSharedMemorySize,
                         GEMM_SMEM);
    cudaFuncSetAttribute(gemm_cp<0>, cudaFuncAttributeMaxDynamicSharedMemorySize,
                         GEMM_SMEM);
    cudaFuncSetAttribute(flash_attn_h, cudaFuncAttributeMaxDynamicSharedMemorySize,
                         FA_SMEM);

    // 1) convert X + weights to half (2^21 float4s / 256 = 8192 blocks)
    cvt_inputs<<<8192, 256>>>((const float4*)x, (const float4*)Wq,
                              (const float4*)Wk, (const float4*)Wv,
                              (const float4*)Wo);

    // 2) fused QKV projections (half in/out)
    const dim3 qkv_grid(24, (Bn * Sn) / BM);     // (24, 32)
    gemm_cp<1><<<qkv_grid, 256, GEMM_SMEM>>>(xh, wh, bq, bk, bv,
                                             qh, kh, vh, nullptr);

    // 3) flash attention (half in, half ctx out)
    dim3 agrid(Sn / 64, Hn, Bn);  // (32, 16, 2)
    flash_attn_h<<<agrid, 128, FA_SMEM>>>(qh, kh, vh, pm, ctx);

    // 4) output projection (half in, fp32 out)
    const dim3 o_grid(Dn / BN, (Bn * Sn) / BM);  // (8, 32)
    gemm_cp<0><<<o_grid, 256, GEMM_SMEM>>>(ctx, wh + (size_t)3 * Dn * Dn,
                                           bo, nullptr, nullptr,
                                           nullptr, nullptr, nullptr, out);
}